// round 13
// baseline (speedup 1.0000x reference)
#include <cuda_runtime.h>
#include <cuda_fp16.h>
#include <math.h>

#define N_NODES 50000
#define N_EDGES 800000
#define IN_F    128
#define HID     32
#define HEADS   8
#define HF      256          // HEADS*HID
#define N_CLASSES 40
#define NEG_SLOPE 0.2f

// ---------------- scratch (device globals; no allocation allowed) ----------------
__device__ __half g_h16[N_NODES * HF];        // fp16 projected features (layers 1-2)
__device__ float  g_Q[N_NODES * HF];          // aggregated features (fp32)
__device__ float  g_el[N_NODES * HEADS];
__device__ float  g_er[N_NODES * HEADS];
__device__ float  g_o1[N_NODES * N_CLASSES];  // output-layer projection
__device__ int    g_cnt[N_NODES];
__device__ int    g_cur[N_NODES];
__device__ int    g_off[N_NODES + 1];
__device__ int    g_ssrc[N_EDGES];
__device__ unsigned g_mx[2];                  // encoded global max of el / er (per layer)

__device__ __forceinline__ float lrelu(float v) { return v > 0.f ? v : NEG_SLOPE * v; }

// order-preserving float<->uint encode for atomicMax
__device__ __forceinline__ unsigned fenc(float f) {
    unsigned u = __float_as_uint(f);
    return (u & 0x80000000u) ? ~u : (u | 0x80000000u);
}
__device__ __forceinline__ float fdec(unsigned u) {
    return (u & 0x80000000u) ? __uint_as_float(u & 0x7fffffffu) : __uint_as_float(~u);
}

// ---------------- CSR build: histogram -> scan -> scatter ----------------
__global__ void hist_k(const int* __restrict__ dst) {
    int i = blockIdx.x * blockDim.x + threadIdx.x;
    if (i < N_EDGES) atomicAdd(&g_cnt[dst[i]], 1);
}

__global__ void scan_k() {   // one block, 1024 threads
    __shared__ int sh[1024];
    int t = threadIdx.x;
    const int n = N_NODES;
    const int chunk = (n + 1023) / 1024;
    int lo = t * chunk;
    int hi = lo + chunk; if (hi > n) hi = n;
    int s = 0;
    for (int i = lo; i < hi; i++) s += g_cnt[i];
    sh[t] = s;
    __syncthreads();
    int own = s;
    for (int d = 1; d < 1024; d <<= 1) {
        int v = (t >= d) ? sh[t - d] : 0;
        __syncthreads();
        sh[t] += v;
        __syncthreads();
    }
    int base = sh[t] - own;
    for (int i = lo; i < hi; i++) { g_off[i] = base; base += g_cnt[i]; }
    if (t == 1023) g_off[n] = sh[1023];
}

__global__ void scatter_k(const int* __restrict__ src, const int* __restrict__ dst) {
    int i = blockIdx.x * blockDim.x + threadIdx.x;
    if (i < N_EDGES) {
        int d = dst[i];
        int pos = atomicAdd(&g_cur[d], 1);
        g_ssrc[g_off[d] + pos] = src[i];
    }
}

// ---------------- TF32 tensor-core GEMM with cp.async double buffering ----------------
// If C16 != null: write fp16 mirror ONLY. Else write fp32 C.
__device__ __forceinline__ void cp_async16(unsigned smem_addr, const void* gptr) {
    asm volatile("cp.async.cg.shared.global [%0], [%1], 16;\n" :: "r"(smem_addr), "l"(gptr));
}
__device__ __forceinline__ void cp_commit() { asm volatile("cp.async.commit_group;\n" ::: "memory"); }
__device__ __forceinline__ void cp_wait1() { asm volatile("cp.async.wait_group 1;\n" ::: "memory"); }
__device__ __forceinline__ void cp_wait0() { asm volatile("cp.async.wait_group 0;\n" ::: "memory"); }

#define TBM 128
#define TBN 64
#define TBK 16
#define KSTR 20
#define BSTR 72

__global__ __launch_bounds__(256) void gemm_tc(const float* __restrict__ A,
                                               const float* __restrict__ B,
                                               float* __restrict__ C,
                                               __half* __restrict__ C16,
                                               int M, int N, int K) {
    __shared__ unsigned As[2][TBM * KSTR];
    __shared__ unsigned Bs[2][TBK * BSTR];
    int tid = threadIdx.x;
    int lane = tid & 31, warp = tid >> 5;
    int wm = warp & 3, wn = warp >> 2;
    int g = lane >> 2, t = lane & 3;
    int row0 = blockIdx.y * TBM, col0 = blockIdx.x * TBN;

    int ar0 = tid >> 2;
    int akq = (tid & 3) << 2;
    int br  = tid >> 4;
    int bnq = (tid & 15) << 2;

    unsigned as_base = (unsigned)__cvta_generic_to_shared(&As[0][0]);
    unsigned bs_base = (unsigned)__cvta_generic_to_shared(&Bs[0][0]);

    float c[2][4][4];
    #pragma unroll
    for (int i = 0; i < 2; i++)
        #pragma unroll
        for (int j = 0; j < 4; j++)
            #pragma unroll
            for (int k = 0; k < 4; k++) c[i][j][k] = 0.f;

    int nk = K / TBK;

    auto load_tile = [&](int buf, int k0) {
        #pragma unroll
        for (int i = 0; i < 2; i++) {
            int r = ar0 + i * 64;
            int gr = row0 + r;
            const float* sp = (gr < M) ? (A + (size_t)gr * K + k0 + akq) : A;
            cp_async16(as_base + (buf * TBM * KSTR + r * KSTR + akq) * 4, sp);
        }
        {
            int gc = col0 + bnq;
            const float* sp = (gc + 3 < N) ? (B + (size_t)(k0 + br) * N + gc) : B;
            cp_async16(bs_base + (buf * TBK * BSTR + br * BSTR + bnq) * 4, sp);
        }
    };

    load_tile(0, 0);
    cp_commit();

    for (int kt = 0; kt < nk; kt++) {
        int buf = kt & 1;
        if (kt + 1 < nk) { load_tile(buf ^ 1, (kt + 1) * TBK); cp_commit(); cp_wait1(); }
        else cp_wait0();
        __syncthreads();

        const unsigned* as = &As[buf][0];
        const unsigned* bs = &Bs[buf][0];
        #pragma unroll
        for (int ks = 0; ks < 2; ks++) {
            int kb = ks * 8;
            unsigned a[2][4], b[4][2];
            #pragma unroll
            for (int mt = 0; mt < 2; mt++) {
                int m0 = wm * 32 + mt * 16;
                a[mt][0] = as[(m0 + g)     * KSTR + kb + t];
                a[mt][1] = as[(m0 + g + 8) * KSTR + kb + t];
                a[mt][2] = as[(m0 + g)     * KSTR + kb + t + 4];
                a[mt][3] = as[(m0 + g + 8) * KSTR + kb + t + 4];
            }
            #pragma unroll
            for (int nt = 0; nt < 4; nt++) {
                int n0 = wn * 32 + nt * 8;
                b[nt][0] = bs[(kb + t)     * BSTR + n0 + g];
                b[nt][1] = bs[(kb + t + 4) * BSTR + n0 + g];
            }
            #pragma unroll
            for (int mt = 0; mt < 2; mt++)
                #pragma unroll
                for (int nt = 0; nt < 4; nt++)
                    asm volatile(
                        "mma.sync.aligned.m16n8k8.row.col.f32.tf32.tf32.f32 "
                        "{%0,%1,%2,%3},{%4,%5,%6,%7},{%8,%9},{%0,%1,%2,%3};"
                        : "+f"(c[mt][nt][0]), "+f"(c[mt][nt][1]),
                          "+f"(c[mt][nt][2]), "+f"(c[mt][nt][3])
                        : "r"(a[mt][0]), "r"(a[mt][1]), "r"(a[mt][2]), "r"(a[mt][3]),
                          "r"(b[nt][0]), "r"(b[nt][1]));
        }
        __syncthreads();
    }

    if (C16) {
        #pragma unroll
        for (int mt = 0; mt < 2; mt++) {
            int rr = row0 + wm * 32 + mt * 16 + g;
            #pragma unroll
            for (int nt = 0; nt < 4; nt++) {
                int cc = col0 + wn * 32 + nt * 8 + 2 * t;
                if (rr < M && cc + 1 < N)
                    *(__half2*)(C16 + (size_t)rr * N + cc) =
                        __floats2half2_rn(c[mt][nt][0], c[mt][nt][1]);
                if (rr + 8 < M && cc + 1 < N)
                    *(__half2*)(C16 + (size_t)(rr + 8) * N + cc) =
                        __floats2half2_rn(c[mt][nt][2], c[mt][nt][3]);
            }
        }
    } else {
        #pragma unroll
        for (int mt = 0; mt < 2; mt++) {
            int rr = row0 + wm * 32 + mt * 16 + g;
            #pragma unroll
            for (int nt = 0; nt < 4; nt++) {
                int cc = col0 + wn * 32 + nt * 8 + 2 * t;
                if (rr < M) {
                    if (cc     < N) C[(size_t)rr * N + cc]     = c[mt][nt][0];
                    if (cc + 1 < N) C[(size_t)rr * N + cc + 1] = c[mt][nt][1];
                }
                if (rr + 8 < M) {
                    if (cc     < N) C[(size_t)(rr + 8) * N + cc]     = c[mt][nt][2];
                    if (cc + 1 < N) C[(size_t)(rr + 8) * N + cc + 1] = c[mt][nt][3];
                }
            }
        }
    }
}

// ---------------- el/er for 8-head layers (fp16 features): warp per node + global-max ----------------
__global__ void elr8_k(const __half* __restrict__ h16, const float* __restrict__ al,
                       const float* __restrict__ ar) {
    __shared__ float sm_el[8], sm_er[8];
    int warp = threadIdx.x >> 5;
    int w = blockIdx.x * 8 + warp;
    int lane = threadIdx.x & 31;
    uint2 hv0 = *(const uint2*)(h16 + (size_t)w * HF + lane * 8);
    uint2 hv1 = *(const uint2*)(h16 + (size_t)w * HF + lane * 8 + 4);
    float2 f0 = __half22float2(*(__half2*)&hv0.x);
    float2 f1 = __half22float2(*(__half2*)&hv0.y);
    float2 f2 = __half22float2(*(__half2*)&hv1.x);
    float2 f3 = __half22float2(*(__half2*)&hv1.y);
    const float4* alp = (const float4*)(al + lane * 8);
    const float4* arp = (const float4*)(ar + lane * 8);
    float4 l0 = alp[0], l1 = alp[1], r0 = arp[0], r1 = arp[1];
    float pel = f0.x*l0.x + f0.y*l0.y + f1.x*l0.z + f1.y*l0.w
              + f2.x*l1.x + f2.y*l1.y + f3.x*l1.z + f3.y*l1.w;
    float per = f0.x*r0.x + f0.y*r0.y + f1.x*r0.z + f1.y*r0.w
              + f2.x*r1.x + f2.y*r1.y + f3.x*r1.z + f3.y*r1.w;
    pel += __shfl_xor_sync(0xffffffffu, pel, 1);
    pel += __shfl_xor_sync(0xffffffffu, pel, 2);
    per += __shfl_xor_sync(0xffffffffu, per, 1);
    per += __shfl_xor_sync(0xffffffffu, per, 2);
    if ((lane & 3) == 0) {
        g_el[w * HEADS + (lane >> 2)] = pel;
        g_er[w * HEADS + (lane >> 2)] = per;
    }
    float mel = pel, mer = per;
    #pragma unroll
    for (int d = 4; d <= 16; d <<= 1) {
        mel = fmaxf(mel, __shfl_xor_sync(0xffffffffu, mel, d));
        mer = fmaxf(mer, __shfl_xor_sync(0xffffffffu, mer, d));
    }
    if (lane == 0) { sm_el[warp] = mel; sm_er[warp] = mer; }
    __syncthreads();
    if (warp == 0) {
        float vel = (lane < 8) ? sm_el[lane] : -INFINITY;
        float ver = (lane < 8) ? sm_er[lane] : -INFINITY;
        #pragma unroll
        for (int d = 1; d <= 4; d <<= 1) {
            vel = fmaxf(vel, __shfl_xor_sync(0xffffffffu, vel, d));
            ver = fmaxf(ver, __shfl_xor_sync(0xffffffffu, ver, d));
        }
        if (lane == 0) {
            atomicMax(&g_mx[0], fenc(vel));
            atomicMax(&g_mx[1], fenc(ver));
        }
    }
}

// ---------------- 8-head aggregation: warp per dst, single pass, 2-edge pipelined ----------------
__global__ void agg8_k(const __half* __restrict__ h16, float* __restrict__ out, int do_elu) {
    int w = (blockIdx.x * blockDim.x + threadIdx.x) >> 5;
    int lane = threadIdx.x & 31;
    if (w >= N_NODES) return;
    int head = lane >> 2;
    float M = lrelu(fdec(g_mx[0]) + fdec(g_mx[1]));   // global upper bound on all logits
    float erd = g_er[w * HEADS + head];
    int b = g_off[w], e = g_off[w + 1];
    float a0=0,a1=0,a2=0,a3=0,a4=0,a5=0,a6=0,a7=0, ss=0;
    int i = b;
    for (; i + 1 < e; i += 2) {
        int s0 = g_ssrc[i], s1 = g_ssrc[i + 1];
        float el0 = g_el[s0 * HEADS + head];
        float el1 = g_el[s1 * HEADS + head];
        uint2 p00 = *(const uint2*)(h16 + (size_t)s0 * HF + lane * 8);
        uint2 p01 = *(const uint2*)(h16 + (size_t)s0 * HF + lane * 8 + 4);
        uint2 p10 = *(const uint2*)(h16 + (size_t)s1 * HF + lane * 8);
        uint2 p11 = *(const uint2*)(h16 + (size_t)s1 * HF + lane * 8 + 4);
        float ex0 = __expf(lrelu(el0 + erd) - M);
        float ex1 = __expf(lrelu(el1 + erd) - M);
        ss += ex0 + ex1;
        float2 u0 = __half22float2(*(__half2*)&p00.x);
        float2 u1 = __half22float2(*(__half2*)&p00.y);
        float2 u2 = __half22float2(*(__half2*)&p01.x);
        float2 u3 = __half22float2(*(__half2*)&p01.y);
        float2 v0 = __half22float2(*(__half2*)&p10.x);
        float2 v1 = __half22float2(*(__half2*)&p10.y);
        float2 v2 = __half22float2(*(__half2*)&p11.x);
        float2 v3 = __half22float2(*(__half2*)&p11.y);
        a0 += ex0*u0.x + ex1*v0.x; a1 += ex0*u0.y + ex1*v0.y;
        a2 += ex0*u1.x + ex1*v1.x; a3 += ex0*u1.y + ex1*v1.y;
        a4 += ex0*u2.x + ex1*v2.x; a5 += ex0*u2.y + ex1*v2.y;
        a6 += ex0*u3.x + ex1*v3.x; a7 += ex0*u3.y + ex1*v3.y;
    }
    for (; i < e; i++) {
        int s = g_ssrc[i];
        float ex = __expf(lrelu(g_el[s * HEADS + head] + erd) - M);
        ss += ex;
        uint2 hv0 = *(const uint2*)(h16 + (size_t)s * HF + lane * 8);
        uint2 hv1 = *(const uint2*)(h16 + (size_t)s * HF + lane * 8 + 4);
        float2 f0 = __half22float2(*(__half2*)&hv0.x);
        float2 f1 = __half22float2(*(__half2*)&hv0.y);
        float2 f2 = __half22float2(*(__half2*)&hv1.x);
        float2 f3 = __half22float2(*(__half2*)&hv1.y);
        a0 += ex*f0.x; a1 += ex*f0.y; a2 += ex*f1.x; a3 += ex*f1.y;
        a4 += ex*f2.x; a5 += ex*f2.y; a6 += ex*f3.x; a7 += ex*f3.y;
    }
    float inv = 1.f / (ss + 1e-16f);
    float r[8] = {a0*inv, a1*inv, a2*inv, a3*inv, a4*inv, a5*inv, a6*inv, a7*inv};
    if (do_elu) {
        #pragma unroll
        for (int k = 0; k < 8; k++) r[k] = r[k] > 0.f ? r[k] : expm1f(r[k]);
    }
    float4* op = (float4*)(out + (size_t)w * HF + lane * 8);
    op[0] = make_float4(r[0], r[1], r[2], r[3]);
    op[1] = make_float4(r[4], r[5], r[6], r[7]);
}

// ---------------- output layer el/er (H=1, F=40): warp per node + global-max reduce ----------------
__global__ void elro_k(const float* __restrict__ h, const float* __restrict__ alo,
                       const float* __restrict__ aro) {
    __shared__ float sm_el[8], sm_er[8];
    int warp = threadIdx.x >> 5;
    int w = blockIdx.x * 8 + warp;
    int lane = threadIdx.x & 31;
    float v1 = h[(size_t)w * N_CLASSES + lane];
    float v2 = (lane < 8) ? h[(size_t)w * N_CLASSES + 32 + lane] : 0.f;
    float pel = v1 * alo[lane] + ((lane < 8) ? v2 * alo[32 + lane] : 0.f);
    float per = v1 * aro[lane] + ((lane < 8) ? v2 * aro[32 + lane] : 0.f);
    #pragma unroll
    for (int d = 16; d >= 1; d >>= 1) {
        pel += __shfl_xor_sync(0xffffffffu, pel, d);
        per += __shfl_xor_sync(0xffffffffu, per, d);
    }
    if (lane == 0) { g_el[w] = pel; g_er[w] = per; sm_el[warp] = pel; sm_er[warp] = per; }
    __syncthreads();
    if (warp == 0) {
        float vel = (lane < 8) ? sm_el[lane] : -INFINITY;
        float ver = (lane < 8) ? sm_er[lane] : -INFINITY;
        #pragma unroll
        for (int d = 1; d <= 4; d <<= 1) {
            vel = fmaxf(vel, __shfl_xor_sync(0xffffffffu, vel, d));
            ver = fmaxf(ver, __shfl_xor_sync(0xffffffffu, ver, d));
        }
        if (lane == 0) {
            atomicMax(&g_mx[0], fenc(vel));
            atomicMax(&g_mx[1], fenc(ver));
        }
    }
}

// ---------------- output aggregation + fused log_softmax: warp per dst, 2-edge pipelined ----------------
__global__ void agg1ls_k(const float* __restrict__ h, float* __restrict__ out) {
    int w = (blockIdx.x * blockDim.x + threadIdx.x) >> 5;
    int lane = threadIdx.x & 31;
    if (w >= N_NODES) return;
    float M = lrelu(fdec(g_mx[0]) + fdec(g_mx[1]));
    float erd = g_er[w];
    int b = g_off[w], e = g_off[w + 1];
    float a0 = 0, a1 = 0, ss = 0;
    int i = b;
    for (; i + 1 < e; i += 2) {
        int s0 = g_ssrc[i], s1 = g_ssrc[i + 1];
        float el0 = g_el[s0], el1 = g_el[s1];
        float f0 = h[(size_t)s0 * N_CLASSES + lane];
        float f1 = h[(size_t)s1 * N_CLASSES + lane];
        float q0 = 0.f, q1 = 0.f;
        if (lane < 8) {
            q0 = h[(size_t)s0 * N_CLASSES + 32 + lane];
            q1 = h[(size_t)s1 * N_CLASSES + 32 + lane];
        }
        float ex0 = __expf(lrelu(el0 + erd) - M);
        float ex1 = __expf(lrelu(el1 + erd) - M);
        ss += ex0 + ex1;
        a0 += ex0 * f0 + ex1 * f1;
        a1 += ex0 * q0 + ex1 * q1;
    }
    for (; i < e; i++) {
        int s = g_ssrc[i];
        float ex = __expf(lrelu(g_el[s] + erd) - M);
        ss += ex;
        a0 += ex * h[(size_t)s * N_CLASSES + lane];
        if (lane < 8) a1 += ex * h[(size_t)s * N_CLASSES + 32 + lane];
    }
    float inv = 1.f / (ss + 1e-16f);
    float v1 = a0 * inv;
    float v2 = (lane < 8) ? a1 * inv : -INFINITY;
    float m = fmaxf(v1, v2);
    #pragma unroll
    for (int d = 16; d >= 1; d >>= 1) m = fmaxf(m, __shfl_xor_sync(0xffffffffu, m, d));
    float s = expf(v1 - m) + ((lane < 8) ? expf(v2 - m) : 0.f);
    #pragma unroll
    for (int d = 16; d >= 1; d >>= 1) s += __shfl_xor_sync(0xffffffffu, s, d);
    float ls = logf(s) + m;
    out[(size_t)w * N_CLASSES + lane] = v1 - ls;
    if (lane < 8) out[(size_t)w * N_CLASSES + 32 + lane] = v2 - ls;
}

// ---------------- host launcher ----------------
static inline int cdiv(int a, int b) { return (a + b - 1) / b; }

extern "C" void kernel_launch(void* const* d_in, const int* in_sizes, int n_in,
                              void* d_out, int out_size) {
    const float* x   = (const float*)d_in[0];
    const int*   src = (const int*)d_in[1];
    const int*   dst = (const int*)d_in[2];
    const float* W1  = (const float*)d_in[3];
    const float* al1 = (const float*)d_in[4];
    const float* ar1 = (const float*)d_in[5];
    const float* W2  = (const float*)d_in[6];
    const float* al2 = (const float*)d_in[7];
    const float* ar2 = (const float*)d_in[8];
    const float* Wo  = (const float*)d_in[9];
    const float* alo = (const float*)d_in[10];
    const float* aro = (const float*)d_in[11];
    float* out = (float*)d_out;

    void *pH16, *pQ, *pO1, *pCnt, *pCur, *pMx;
    cudaGetSymbolAddress(&pH16, g_h16);
    cudaGetSymbolAddress(&pQ, g_Q);
    cudaGetSymbolAddress(&pO1, g_o1);
    cudaGetSymbolAddress(&pCnt, g_cnt);
    cudaGetSymbolAddress(&pCur, g_cur);
    cudaGetSymbolAddress(&pMx, g_mx);

    // CSR build (by dst)
    cudaMemsetAsync(pCnt, 0, N_NODES * sizeof(int));
    cudaMemsetAsync(pCur, 0, N_NODES * sizeof(int));
    int eb = cdiv(N_EDGES, 256);
    hist_k<<<eb, 256>>>(dst);
    scan_k<<<1, 1024>>>();
    scatter_k<<<eb, 256>>>(src, dst);

    int nwb = N_NODES * 32 / 256;            // 6250 blocks, 8 warps each
    dim3 g1(cdiv(HF, TBN), cdiv(N_NODES, TBM));
    dim3 g3(cdiv(N_CLASSES, TBN), cdiv(N_NODES, TBM));

    // layer 1: GEMM -> fp16 features only; logits from fp16
    gemm_tc<<<g1, 256>>>(x, W1, nullptr, (__half*)pH16, N_NODES, HF, IN_F);
    cudaMemsetAsync(pMx, 0, 2 * sizeof(unsigned));
    elr8_k<<<nwb, 256>>>((const __half*)pH16, al1, ar1);
    agg8_k<<<nwb, 256>>>((const __half*)pH16, (float*)pQ, 1);

    // layer 2
    gemm_tc<<<g1, 256>>>((const float*)pQ, W2, nullptr, (__half*)pH16, N_NODES, HF, HF);
    cudaMemsetAsync(pMx, 0, 2 * sizeof(unsigned));
    elr8_k<<<nwb, 256>>>((const __half*)pH16, al2, ar2);
    agg8_k<<<nwb, 256>>>((const __half*)pH16, (float*)pQ, 1);

    // output layer (all fp32)
    gemm_tc<<<g3, 256>>>((const float*)pQ, Wo, (float*)pO1, (__half*)nullptr, N_NODES, N_CLASSES, HF);
    cudaMemsetAsync(pMx, 0, 2 * sizeof(unsigned));
    elro_k<<<nwb, 256>>>((const float*)pO1, alo, aro);
    agg1ls_k<<<nwb, 256>>>((const float*)pO1, out);
}

// round 14
// speedup vs baseline: 1.4143x; 1.4143x over previous
#include <cuda_runtime.h>
#include <cuda_fp16.h>
#include <math.h>

#define N_NODES 50000
#define N_EDGES 800000
#define IN_F    128
#define HID     32
#define HEADS   8
#define HF      256          // HEADS*HID
#define N_CLASSES 40
#define NEG_SLOPE 0.2f

// ---------------- scratch (device globals; no allocation allowed) ----------------
__device__ __half g_h16[N_NODES * HF];        // fp16 projected features P (layers 1-2)
__device__ __half g_Qh[N_NODES * HF];         // fp16 aggregated features Q (GEMM A input)
__device__ __half g_x16[N_NODES * IN_F];      // fp16 copy of input x
__device__ __half g_W1T[HF * IN_F];           // W1^T fp16 [n][k]
__device__ __half g_W2T[HF * HF];             // W2^T fp16 [n][k]
__device__ __half g_WoT[64 * HF];             // Wo^T fp16 [n][k], padded 40->64 rows
__device__ float  g_el[N_NODES * HEADS];
__device__ float  g_er[N_NODES * HEADS];
__device__ float  g_o1[N_NODES * N_CLASSES];  // output-layer projection (fp32)
__device__ int    g_cnt[N_NODES];
__device__ int    g_cur[N_NODES];
__device__ int    g_off[N_NODES + 1];
__device__ int    g_ssrc[N_EDGES];
__device__ unsigned g_mx[2];                  // encoded global max of el / er (per layer)

__device__ __forceinline__ float lrelu(float v) { return v > 0.f ? v : NEG_SLOPE * v; }

// order-preserving float<->uint encode for atomicMax
__device__ __forceinline__ unsigned fenc(float f) {
    unsigned u = __float_as_uint(f);
    return (u & 0x80000000u) ? ~u : (u | 0x80000000u);
}
__device__ __forceinline__ float fdec(unsigned u) {
    return (u & 0x80000000u) ? __uint_as_float(u & 0x7fffffffu) : __uint_as_float(~u);
}

// ---------------- converters ----------------
__global__ void cvtA_k(const float* __restrict__ src, __half* __restrict__ dst, int n) {
    int i = blockIdx.x * blockDim.x + threadIdx.x;
    if (i < n) dst[i] = __float2half_rn(src[i]);
}

// BT[n*K + k] = (n < N) ? W[k*N + n] : 0   for n in [0, NBT)
__global__ void cvtBT_k(const float* __restrict__ W, __half* __restrict__ BT,
                        int K, int N, int NBT) {
    int i = blockIdx.x * blockDim.x + threadIdx.x;
    if (i >= K * NBT) return;
    int n = i / K, k = i % K;
    BT[i] = __float2half_rn((n < N) ? W[k * N + n] : 0.f);
}

// ---------------- CSR build: histogram -> scan -> scatter ----------------
__global__ void hist_k(const int* __restrict__ dst) {
    int i = blockIdx.x * blockDim.x + threadIdx.x;
    if (i < N_EDGES) atomicAdd(&g_cnt[dst[i]], 1);
}

__global__ void scan_k() {   // one block, 1024 threads
    __shared__ int sh[1024];
    int t = threadIdx.x;
    const int n = N_NODES;
    const int chunk = (n + 1023) / 1024;
    int lo = t * chunk;
    int hi = lo + chunk; if (hi > n) hi = n;
    int s = 0;
    for (int i = lo; i < hi; i++) s += g_cnt[i];
    sh[t] = s;
    __syncthreads();
    int own = s;
    for (int d = 1; d < 1024; d <<= 1) {
        int v = (t >= d) ? sh[t - d] : 0;
        __syncthreads();
        sh[t] += v;
        __syncthreads();
    }
    int base = sh[t] - own;
    for (int i = lo; i < hi; i++) { g_off[i] = base; base += g_cnt[i]; }
    if (t == 1023) g_off[n] = sh[1023];
}

__global__ void scatter_k(const int* __restrict__ src, const int* __restrict__ dst) {
    int i = blockIdx.x * blockDim.x + threadIdx.x;
    if (i < N_EDGES) {
        int d = dst[i];
        int pos = atomicAdd(&g_cur[d], 1);
        g_ssrc[g_off[d] + pos] = src[i];
    }
}

// ---------------- fp16 tensor-core GEMM (m16n8k16), cp.async double buffered ----------------
// A fp16 row-major [M,K]; BT fp16 [NBT][K] (B transposed, rows padded to >=64 multiples).
// If C16 != null: write fp16 C16[M,N]. Else write fp32 C[M,N] (bounds-checked vs N).
__device__ __forceinline__ void cp_async16(unsigned smem_addr, const void* gptr) {
    asm volatile("cp.async.cg.shared.global [%0], [%1], 16;\n" :: "r"(smem_addr), "l"(gptr));
}
__device__ __forceinline__ void cp_commit() { asm volatile("cp.async.commit_group;\n" ::: "memory"); }
__device__ __forceinline__ void cp_wait1() { asm volatile("cp.async.wait_group 1;\n" ::: "memory"); }
__device__ __forceinline__ void cp_wait0() { asm volatile("cp.async.wait_group 0;\n" ::: "memory"); }

#define TBM 128
#define TBN 64
#define TBK 32        // halves per k-block
#define ASTRH 40      // A smem row stride in halves (banks: 20g+t all distinct)
#define BSTRH 40      // B smem row stride in halves

__global__ __launch_bounds__(256) void gemm_h(const __half* __restrict__ A,
                                              const __half* __restrict__ BT,
                                              float* __restrict__ C,
                                              __half* __restrict__ C16,
                                              int M, int N, int K) {
    __shared__ __half As[2][TBM * ASTRH];
    __shared__ __half Bs[2][TBN * BSTRH];
    int tid = threadIdx.x;
    int lane = tid & 31, warp = tid >> 5;
    int wm = warp & 3, wn = warp >> 2;           // 4 (m) x 2 (n) warps
    int g = lane >> 2, t = lane & 3;
    int row0 = blockIdx.y * TBM, col0 = blockIdx.x * TBN;

    // staging coords: A 128 rows x 4 chunks(8 halves) in 2 passes; B 64 rows x 4 chunks
    int ar = tid >> 2;          // 0..63
    int ac = (tid & 3) << 3;    // 0,8,16,24 halves
    unsigned as_base = (unsigned)__cvta_generic_to_shared(&As[0][0]);
    unsigned bs_base = (unsigned)__cvta_generic_to_shared(&Bs[0][0]);

    float c[2][4][4];
    #pragma unroll
    for (int i = 0; i < 2; i++)
        #pragma unroll
        for (int j = 0; j < 4; j++)
            #pragma unroll
            for (int k = 0; k < 4; k++) c[i][j][k] = 0.f;

    int nk = K / TBK;

    auto load_tile = [&](int buf, int k0) {
        #pragma unroll
        for (int i = 0; i < 2; i++) {
            int r = ar + i * 64;
            int gr = row0 + r;
            const __half* sp = (gr < M) ? (A + (size_t)gr * K + k0 + ac) : A;
            cp_async16(as_base + (buf * TBM * ASTRH + r * ASTRH + ac) * 2, sp);
        }
        {
            const __half* sp = BT + (size_t)(col0 + ar) * K + k0 + ac;  // BT rows padded
            cp_async16(bs_base + (buf * TBN * BSTRH + ar * BSTRH + ac) * 2, sp);
        }
    };

    load_tile(0, 0);
    cp_commit();

    for (int kt = 0; kt < nk; kt++) {
        int buf = kt & 1;
        if (kt + 1 < nk) { load_tile(buf ^ 1, (kt + 1) * TBK); cp_commit(); cp_wait1(); }
        else cp_wait0();
        __syncthreads();

        const __half* as = &As[buf][0];
        const __half* bs = &Bs[buf][0];
        #pragma unroll
        for (int ks = 0; ks < 2; ks++) {
            int kb = ks * 16;
            unsigned a[2][4], b[4][2];
            #pragma unroll
            for (int mt = 0; mt < 2; mt++) {
                int m0 = wm * 32 + mt * 16;
                a[mt][0] = *(const unsigned*)&as[(m0 + g)     * ASTRH + kb + 2 * t];
                a[mt][1] = *(const unsigned*)&as[(m0 + g + 8) * ASTRH + kb + 2 * t];
                a[mt][2] = *(const unsigned*)&as[(m0 + g)     * ASTRH + kb + 2 * t + 8];
                a[mt][3] = *(const unsigned*)&as[(m0 + g + 8) * ASTRH + kb + 2 * t + 8];
            }
            #pragma unroll
            for (int nt = 0; nt < 4; nt++) {
                int n0 = wn * 32 + nt * 8;
                b[nt][0] = *(const unsigned*)&bs[(n0 + g) * BSTRH + kb + 2 * t];
                b[nt][1] = *(const unsigned*)&bs[(n0 + g) * BSTRH + kb + 2 * t + 8];
            }
            #pragma unroll
            for (int mt = 0; mt < 2; mt++)
                #pragma unroll
                for (int nt = 0; nt < 4; nt++)
                    asm volatile(
                        "mma.sync.aligned.m16n8k16.row.col.f32.f16.f16.f32 "
                        "{%0,%1,%2,%3},{%4,%5,%6,%7},{%8,%9},{%0,%1,%2,%3};"
                        : "+f"(c[mt][nt][0]), "+f"(c[mt][nt][1]),
                          "+f"(c[mt][nt][2]), "+f"(c[mt][nt][3])
                        : "r"(a[mt][0]), "r"(a[mt][1]), "r"(a[mt][2]), "r"(a[mt][3]),
                          "r"(b[nt][0]), "r"(b[nt][1]));
        }
        __syncthreads();
    }

    // epilogue: c0:(g,2t) c1:(g,2t+1) c2:(g+8,2t) c3:(g+8,2t+1)
    if (C16) {
        #pragma unroll
        for (int mt = 0; mt < 2; mt++) {
            int rr = row0 + wm * 32 + mt * 16 + g;
            #pragma unroll
            for (int nt = 0; nt < 4; nt++) {
                int cc = col0 + wn * 32 + nt * 8 + 2 * t;
                if (rr < M && cc + 1 < N)
                    *(__half2*)(C16 + (size_t)rr * N + cc) =
                        __floats2half2_rn(c[mt][nt][0], c[mt][nt][1]);
                if (rr + 8 < M && cc + 1 < N)
                    *(__half2*)(C16 + (size_t)(rr + 8) * N + cc) =
                        __floats2half2_rn(c[mt][nt][2], c[mt][nt][3]);
            }
        }
    } else {
        #pragma unroll
        for (int mt = 0; mt < 2; mt++) {
            int rr = row0 + wm * 32 + mt * 16 + g;
            #pragma unroll
            for (int nt = 0; nt < 4; nt++) {
                int cc = col0 + wn * 32 + nt * 8 + 2 * t;
                if (rr < M) {
                    if (cc     < N) C[(size_t)rr * N + cc]     = c[mt][nt][0];
                    if (cc + 1 < N) C[(size_t)rr * N + cc + 1] = c[mt][nt][1];
                }
                if (rr + 8 < M) {
                    if (cc     < N) C[(size_t)(rr + 8) * N + cc]     = c[mt][nt][2];
                    if (cc + 1 < N) C[(size_t)(rr + 8) * N + cc + 1] = c[mt][nt][3];
                }
            }
        }
    }
}

// ---------------- el/er for 8-head layers (fp16 features): warp per node + global-max ----------------
__global__ void elr8_k(const __half* __restrict__ h16, const float* __restrict__ al,
                       const float* __restrict__ ar) {
    __shared__ float sm_el[8], sm_er[8];
    int warp = threadIdx.x >> 5;
    int w = blockIdx.x * 8 + warp;
    int lane = threadIdx.x & 31;
    uint2 hv0 = *(const uint2*)(h16 + (size_t)w * HF + lane * 8);
    uint2 hv1 = *(const uint2*)(h16 + (size_t)w * HF + lane * 8 + 4);
    float2 f0 = __half22float2(*(__half2*)&hv0.x);
    float2 f1 = __half22float2(*(__half2*)&hv0.y);
    float2 f2 = __half22float2(*(__half2*)&hv1.x);
    float2 f3 = __half22float2(*(__half2*)&hv1.y);
    const float4* alp = (const float4*)(al + lane * 8);
    const float4* arp = (const float4*)(ar + lane * 8);
    float4 l0 = alp[0], l1 = alp[1], r0 = arp[0], r1 = arp[1];
    float pel = f0.x*l0.x + f0.y*l0.y + f1.x*l0.z + f1.y*l0.w
              + f2.x*l1.x + f2.y*l1.y + f3.x*l1.z + f3.y*l1.w;
    float per = f0.x*r0.x + f0.y*r0.y + f1.x*r0.z + f1.y*r0.w
              + f2.x*r1.x + f2.y*r1.y + f3.x*r1.z + f3.y*r1.w;
    pel += __shfl_xor_sync(0xffffffffu, pel, 1);
    pel += __shfl_xor_sync(0xffffffffu, pel, 2);
    per += __shfl_xor_sync(0xffffffffu, per, 1);
    per += __shfl_xor_sync(0xffffffffu, per, 2);
    if ((lane & 3) == 0) {
        g_el[w * HEADS + (lane >> 2)] = pel;
        g_er[w * HEADS + (lane >> 2)] = per;
    }
    float mel = pel, mer = per;
    #pragma unroll
    for (int d = 4; d <= 16; d <<= 1) {
        mel = fmaxf(mel, __shfl_xor_sync(0xffffffffu, mel, d));
        mer = fmaxf(mer, __shfl_xor_sync(0xffffffffu, mer, d));
    }
    if (lane == 0) { sm_el[warp] = mel; sm_er[warp] = mer; }
    __syncthreads();
    if (warp == 0) {
        float vel = (lane < 8) ? sm_el[lane] : -INFINITY;
        float ver = (lane < 8) ? sm_er[lane] : -INFINITY;
        #pragma unroll
        for (int d = 1; d <= 4; d <<= 1) {
            vel = fmaxf(vel, __shfl_xor_sync(0xffffffffu, vel, d));
            ver = fmaxf(ver, __shfl_xor_sync(0xffffffffu, ver, d));
        }
        if (lane == 0) {
            atomicMax(&g_mx[0], fenc(vel));
            atomicMax(&g_mx[1], fenc(ver));
        }
    }
}

// ---------------- 8-head aggregation: warp per dst, single pass, fp16 in/out ----------------
__global__ void agg8_k(const __half* __restrict__ h16, __half* __restrict__ out, int do_elu) {
    int w = (blockIdx.x * blockDim.x + threadIdx.x) >> 5;
    int lane = threadIdx.x & 31;
    if (w >= N_NODES) return;
    int head = lane >> 2;
    float M = lrelu(fdec(g_mx[0]) + fdec(g_mx[1]));   // global upper bound on all logits
    float erd = g_er[w * HEADS + head];
    int b = g_off[w], e = g_off[w + 1];
    float a0=0,a1=0,a2=0,a3=0,a4=0,a5=0,a6=0,a7=0, ss=0;
    for (int i = b; i < e; i++) {
        int s = g_ssrc[i];
        float ex = __expf(lrelu(g_el[s * HEADS + head] + erd) - M);
        ss += ex;
        uint2 hv0 = *(const uint2*)(h16 + (size_t)s * HF + lane * 8);
        uint2 hv1 = *(const uint2*)(h16 + (size_t)s * HF + lane * 8 + 4);
        float2 f0 = __half22float2(*(__half2*)&hv0.x);
        float2 f1 = __half22float2(*(__half2*)&hv0.y);
        float2 f2 = __half22float2(*(__half2*)&hv1.x);
        float2 f3 = __half22float2(*(__half2*)&hv1.y);
        a0 += ex*f0.x; a1 += ex*f0.y; a2 += ex*f1.x; a3 += ex*f1.y;
        a4 += ex*f2.x; a5 += ex*f2.y; a6 += ex*f3.x; a7 += ex*f3.y;
    }
    float inv = 1.f / (ss + 1e-16f);
    float r[8] = {a0*inv, a1*inv, a2*inv, a3*inv, a4*inv, a5*inv, a6*inv, a7*inv};
    if (do_elu) {
        #pragma unroll
        for (int k = 0; k < 8; k++) r[k] = r[k] > 0.f ? r[k] : expm1f(r[k]);
    }
    __half2 h01 = __floats2half2_rn(r[0], r[1]);
    __half2 h23 = __floats2half2_rn(r[2], r[3]);
    __half2 h45 = __floats2half2_rn(r[4], r[5]);
    __half2 h67 = __floats2half2_rn(r[6], r[7]);
    uint4 pk;
    pk.x = *(unsigned*)&h01; pk.y = *(unsigned*)&h23;
    pk.z = *(unsigned*)&h45; pk.w = *(unsigned*)&h67;
    *(uint4*)(out + (size_t)w * HF + lane * 8) = pk;
}

// ---------------- output layer el/er (H=1, F=40): warp per node + global-max reduce ----------------
__global__ void elro_k(const float* __restrict__ h, const float* __restrict__ alo,
                       const float* __restrict__ aro) {
    __shared__ float sm_el[8], sm_er[8];
    int warp = threadIdx.x >> 5;
    int w = blockIdx.x * 8 + warp;
    int lane = threadIdx.x & 31;
    float v1 = h[(size_t)w * N_CLASSES + lane];
    float v2 = (lane < 8) ? h[(size_t)w * N_CLASSES + 32 + lane] : 0.f;
    float pel = v1 * alo[lane] + ((lane < 8) ? v2 * alo[32 + lane] : 0.f);
    float per = v1 * aro[lane] + ((lane < 8) ? v2 * aro[32 + lane] : 0.f);
    #pragma unroll
    for (int d = 16; d >= 1; d >>= 1) {
        pel += __shfl_xor_sync(0xffffffffu, pel, d);
        per += __shfl_xor_sync(0xffffffffu, per, d);
    }
    if (lane == 0) { g_el[w] = pel; g_er[w] = per; sm_el[warp] = pel; sm_er[warp] = per; }
    __syncthreads();
    if (warp == 0) {
        float vel = (lane < 8) ? sm_el[lane] : -INFINITY;
        float ver = (lane < 8) ? sm_er[lane] : -INFINITY;
        #pragma unroll
        for (int d = 1; d <= 4; d <<= 1) {
            vel = fmaxf(vel, __shfl_xor_sync(0xffffffffu, vel, d));
            ver = fmaxf(ver, __shfl_xor_sync(0xffffffffu, ver, d));
        }
        if (lane == 0) {
            atomicMax(&g_mx[0], fenc(vel));
            atomicMax(&g_mx[1], fenc(ver));
        }
    }
}

// ---------------- output aggregation + fused log_softmax: warp per dst, single pass ----------------
__global__ void agg1ls_k(const float* __restrict__ h, float* __restrict__ out) {
    int w = (blockIdx.x * blockDim.x + threadIdx.x) >> 5;
    int lane = threadIdx.x & 31;
    if (w >= N_NODES) return;
    float M = lrelu(fdec(g_mx[0]) + fdec(g_mx[1]));
    float erd = g_er[w];
    int b = g_off[w], e = g_off[w + 1];
    float a0 = 0, a1 = 0, ss = 0;
    for (int i = b; i < e; i++) {
        int s = g_ssrc[i];
        float ex = __expf(lrelu(g_el[s] + erd) - M);
        ss += ex;
        a0 += ex * h[(size_t)s * N_CLASSES + lane];
        if (lane < 8) a1 += ex * h[(size_t)s * N_CLASSES + 32 + lane];
    }
    float inv = 1.f / (ss + 1e-16f);
    float v1 = a0 * inv;
    float v2 = (lane < 8) ? a1 * inv : -INFINITY;
    float m = fmaxf(v1, v2);
    #pragma unroll
    for (int d = 16; d >= 1; d >>= 1) m = fmaxf(m, __shfl_xor_sync(0xffffffffu, m, d));
    float s = expf(v1 - m) + ((lane < 8) ? expf(v2 - m) : 0.f);
    #pragma unroll
    for (int d = 16; d >= 1; d >>= 1) s += __shfl_xor_sync(0xffffffffu, s, d);
    float ls = logf(s) + m;
    out[(size_t)w * N_CLASSES + lane] = v1 - ls;
    if (lane < 8) out[(size_t)w * N_CLASSES + 32 + lane] = v2 - ls;
}

// ---------------- host launcher ----------------
static inline int cdiv(int a, int b) { return (a + b - 1) / b; }

extern "C" void kernel_launch(void* const* d_in, const int* in_sizes, int n_in,
                              void* d_out, int out_size) {
    const float* x   = (const float*)d_in[0];
    const int*   src = (const int*)d_in[1];
    const int*   dst = (const int*)d_in[2];
    const float* W1  = (const float*)d_in[3];
    const float* al1 = (const float*)d_in[4];
    const float* ar1 = (const float*)d_in[5];
    const float* W2  = (const float*)d_in[6];
    const float* al2 = (const float*)d_in[7];
    const float* ar2 = (const float*)d_in[8];
    const float* Wo  = (const float*)d_in[9];
    const float* alo = (const float*)d_in[10];
    const float* aro = (const float*)d_in[11];
    float* out = (float*)d_out;

    void *pH16, *pQh, *pX16, *pW1T, *pW2T, *pWoT, *pO1, *pCnt, *pCur, *pMx;
    cudaGetSymbolAddress(&pH16, g_h16);
    cudaGetSymbolAddress(&pQh, g_Qh);
    cudaGetSymbolAddress(&pX16, g_x16);
    cudaGetSymbolAddress(&pW1T, g_W1T);
    cudaGetSymbolAddress(&pW2T, g_W2T);
    cudaGetSymbolAddress(&pWoT, g_WoT);
    cudaGetSymbolAddress(&pO1, g_o1);
    cudaGetSymbolAddress(&pCnt, g_cnt);
    cudaGetSymbolAddress(&pCur, g_cur);
    cudaGetSymbolAddress(&pMx, g_mx);

    // conversions (independent; issue first)
    cvtA_k<<<cdiv(N_NODES * IN_F, 256), 256>>>(x, (__half*)pX16, N_NODES * IN_F);
    cvtBT_k<<<cdiv(IN_F * HF, 256), 256>>>(W1, (__half*)pW1T, IN_F, HF, HF);
    cvtBT_k<<<cdiv(HF * HF, 256), 256>>>(W2, (__half*)pW2T, HF, HF, HF);
    cvtBT_k<<<cdiv(HF * 64, 256), 256>>>(Wo, (__half*)pWoT, HF, N_CLASSES, 64);

    // CSR build (by dst)
    cudaMemsetAsync(pCnt, 0, N_NODES * sizeof(int));
    cudaMemsetAsync(pCur, 0, N_NODES * sizeof(int));
    int eb = cdiv(N_EDGES, 256);
    hist_k<<<eb, 256>>>(dst);
    scan_k<<<1, 1024>>>();
    scatter_k<<<eb, 256>>>(src, dst);

    int nwb = N_NODES * 32 / 256;            // 6250 blocks, 8 warps each
    dim3 g1(cdiv(HF, TBN), cdiv(N_NODES, TBM));      // 4 x 391
    dim3 g3(1, cdiv(N_NODES, TBM));                   // N=40 -> 1 col tile

    // layer 1: fp16 GEMM -> fp16 features
    gemm_h<<<g1, 256>>>((const __half*)pX16, (const __half*)pW1T, nullptr, (__half*)pH16,
                        N_NODES, HF, IN_F);
    cudaMemsetAsync(pMx, 0, 2 * sizeof(unsigned));
    elr8_k<<<nwb, 256>>>((const __half*)pH16, al1, ar1);
    agg8_k<<<nwb, 256>>>((const __half*)pH16, (__half*)pQh, 1);

    // layer 2
    gemm_h<<<g1, 256>>>((const __half*)pQh, (const __half*)pW2T, nullptr, (__half*)pH16,
                        N_NODES, HF, HF);
    cudaMemsetAsync(pMx, 0, 2 * sizeof(unsigned));
    elr8_k<<<nwb, 256>>>((const __half*)pH16, al2, ar2);
    agg8_k<<<nwb, 256>>>((const __half*)pH16, (__half*)pQh, 1);

    // output layer: fp16 GEMM -> fp32 logits; rest fp32
    gemm_h<<<g3, 256>>>((const __half*)pQh, (const __half*)pWoT, (float*)pO1, (__half*)nullptr,
                        N_NODES, N_CLASSES, HF);
    cudaMemsetAsync(pMx, 0, 2 * sizeof(unsigned));
    elro_k<<<nwb, 256>>>((const float*)pO1, alo, aro);
    agg1ls_k<<<nwb, 256>>>((const float*)pO1, out);
}

// round 15
// speedup vs baseline: 1.4846x; 1.0497x over previous
#include <cuda_runtime.h>
#include <cuda_fp16.h>
#include <math.h>

#define N_NODES 50000
#define N_EDGES 800000
#define IN_F    128
#define HID     32
#define HEADS   8
#define HF      256          // HEADS*HID
#define N_CLASSES 40
#define NEG_SLOPE 0.2f

// ---------------- scratch (device globals; no allocation allowed) ----------------
__device__ __half g_h16[N_NODES * HF];        // fp16 projected features P (layers 1-2)
__device__ __half g_Qh[N_NODES * HF];         // fp16 aggregated features Q (GEMM A input)
__device__ __half g_x16[N_NODES * IN_F];      // fp16 copy of input x
__device__ __half g_W1T[HF * IN_F];           // W1^T fp16 [n][k]
__device__ __half g_W2T[HF * HF];             // W2^T fp16 [n][k]
__device__ __half g_WoT[64 * HF];             // Wo^T fp16 [n][k], padded 40->64 rows
__device__ float  g_el[N_NODES * HEADS];
__device__ float  g_er[N_NODES * HEADS];
__device__ float  g_o1[N_NODES * N_CLASSES];  // output-layer projection (fp32)
__device__ int    g_cnt[N_NODES];
__device__ int    g_cur[N_NODES];
__device__ int    g_off[N_NODES + 1];
__device__ int    g_ssrc[N_EDGES];
__device__ unsigned g_mx[2];                  // encoded global max of el / er (per layer)

__device__ __forceinline__ float lrelu(float v) { return v > 0.f ? v : NEG_SLOPE * v; }

// order-preserving float<->uint encode for atomicMax
__device__ __forceinline__ unsigned fenc(float f) {
    unsigned u = __float_as_uint(f);
    return (u & 0x80000000u) ? ~u : (u | 0x80000000u);
}
__device__ __forceinline__ float fdec(unsigned u) {
    return (u & 0x80000000u) ? __uint_as_float(u & 0x7fffffffu) : __uint_as_float(~u);
}

// ---------------- converters ----------------
// also zeroes g_cnt/g_cur (runs before hist_k)
__global__ void cvtA_k(const float* __restrict__ src, __half* __restrict__ dst, int n) {
    int i = blockIdx.x * blockDim.x + threadIdx.x;
    if (i < n) dst[i] = __float2half_rn(src[i]);
    if (i < N_NODES) { g_cnt[i] = 0; g_cur[i] = 0; }
}

// BT[n*K + k] = (n < N) ? W[k*N + n] : 0   for n in [0, NBT)
__global__ void cvtBT_k(const float* __restrict__ W, __half* __restrict__ BT,
                        int K, int N, int NBT) {
    int i = blockIdx.x * blockDim.x + threadIdx.x;
    if (i >= K * NBT) return;
    int n = i / K, k = i % K;
    BT[i] = __float2half_rn((n < N) ? W[k * N + n] : 0.f);
}

// ---------------- CSR build: histogram -> scan -> scatter ----------------
__global__ void hist_k(const int* __restrict__ dst) {
    int i = blockIdx.x * blockDim.x + threadIdx.x;
    if (i < N_EDGES) atomicAdd(&g_cnt[dst[i]], 1);
}

__global__ void scan_k() {   // one block, 1024 threads
    __shared__ int sh[1024];
    int t = threadIdx.x;
    const int n = N_NODES;
    const int chunk = (n + 1023) / 1024;
    int lo = t * chunk;
    int hi = lo + chunk; if (hi > n) hi = n;
    int s = 0;
    for (int i = lo; i < hi; i++) s += g_cnt[i];
    sh[t] = s;
    __syncthreads();
    int own = s;
    for (int d = 1; d < 1024; d <<= 1) {
        int v = (t >= d) ? sh[t - d] : 0;
        __syncthreads();
        sh[t] += v;
        __syncthreads();
    }
    int base = sh[t] - own;
    for (int i = lo; i < hi; i++) { g_off[i] = base; base += g_cnt[i]; }
    if (t == 1023) g_off[n] = sh[1023];
}

__global__ void scatter_k(const int* __restrict__ src, const int* __restrict__ dst) {
    int i = blockIdx.x * blockDim.x + threadIdx.x;
    if (i < N_EDGES) {
        int d = dst[i];
        int pos = atomicAdd(&g_cur[d], 1);
        g_ssrc[g_off[d] + pos] = src[i];
    }
}

// ---------------- fp16 tensor-core GEMM (m16n8k16), cp.async double buffered ----------------
// A fp16 row-major [M,K]; BT fp16 [NBT][K] (B transposed, rows padded).
// If C16 != null: write fp16 C16[M,N]. Else write fp32 C[M,N] (bounds-checked vs N).
// reset_mx: thread(0,0) zeroes g_mx (consumed by elr/elro which launch after this kernel).
__device__ __forceinline__ void cp_async16(unsigned smem_addr, const void* gptr) {
    asm volatile("cp.async.cg.shared.global [%0], [%1], 16;\n" :: "r"(smem_addr), "l"(gptr));
}
__device__ __forceinline__ void cp_commit() { asm volatile("cp.async.commit_group;\n" ::: "memory"); }
__device__ __forceinline__ void cp_wait1() { asm volatile("cp.async.wait_group 1;\n" ::: "memory"); }
__device__ __forceinline__ void cp_wait0() { asm volatile("cp.async.wait_group 0;\n" ::: "memory"); }

#define TBM 128
#define TBN 64
#define TBK 32        // halves per k-block
#define ASTRH 40      // A smem row stride in halves
#define BSTRH 40      // B smem row stride in halves

__global__ __launch_bounds__(256) void gemm_h(const __half* __restrict__ A,
                                              const __half* __restrict__ BT,
                                              float* __restrict__ C,
                                              __half* __restrict__ C16,
                                              int M, int N, int K, int reset_mx) {
    __shared__ __half As[2][TBM * ASTRH];
    __shared__ __half Bs[2][TBN * BSTRH];
    int tid = threadIdx.x;
    if (reset_mx && tid == 0 && blockIdx.x == 0 && blockIdx.y == 0) {
        g_mx[0] = 0u; g_mx[1] = 0u;
    }
    int lane = tid & 31, warp = tid >> 5;
    int wm = warp & 3, wn = warp >> 2;           // 4 (m) x 2 (n) warps
    int g = lane >> 2, t = lane & 3;
    int row0 = blockIdx.y * TBM, col0 = blockIdx.x * TBN;

    int ar = tid >> 2;          // 0..63
    int ac = (tid & 3) << 3;    // 0,8,16,24 halves
    unsigned as_base = (unsigned)__cvta_generic_to_shared(&As[0][0]);
    unsigned bs_base = (unsigned)__cvta_generic_to_shared(&Bs[0][0]);

    float c[2][4][4];
    #pragma unroll
    for (int i = 0; i < 2; i++)
        #pragma unroll
        for (int j = 0; j < 4; j++)
            #pragma unroll
            for (int k = 0; k < 4; k++) c[i][j][k] = 0.f;

    int nk = K / TBK;

    auto load_tile = [&](int buf, int k0) {
        #pragma unroll
        for (int i = 0; i < 2; i++) {
            int r = ar + i * 64;
            int gr = row0 + r;
            const __half* sp = (gr < M) ? (A + (size_t)gr * K + k0 + ac) : A;
            cp_async16(as_base + (buf * TBM * ASTRH + r * ASTRH + ac) * 2, sp);
        }
        {
            const __half* sp = BT + (size_t)(col0 + ar) * K + k0 + ac;
            cp_async16(bs_base + (buf * TBN * BSTRH + ar * BSTRH + ac) * 2, sp);
        }
    };

    load_tile(0, 0);
    cp_commit();

    for (int kt = 0; kt < nk; kt++) {
        int buf = kt & 1;
        if (kt + 1 < nk) { load_tile(buf ^ 1, (kt + 1) * TBK); cp_commit(); cp_wait1(); }
        else cp_wait0();
        __syncthreads();

        const __half* as = &As[buf][0];
        const __half* bs = &Bs[buf][0];
        #pragma unroll
        for (int ks = 0; ks < 2; ks++) {
            int kb = ks * 16;
            unsigned a[2][4], b[4][2];
            #pragma unroll
            for (int mt = 0; mt < 2; mt++) {
                int m0 = wm * 32 + mt * 16;
                a[mt][0] = *(const unsigned*)&as[(m0 + g)     * ASTRH + kb + 2 * t];
                a[mt][1] = *(const unsigned*)&as[(m0 + g + 8) * ASTRH + kb + 2 * t];
                a[mt][2] = *(const unsigned*)&as[(m0 + g)     * ASTRH + kb + 2 * t + 8];
                a[mt][3] = *(const unsigned*)&as[(m0 + g + 8) * ASTRH + kb + 2 * t + 8];
            }
            #pragma unroll
            for (int nt = 0; nt < 4; nt++) {
                int n0 = wn * 32 + nt * 8;
                b[nt][0] = *(const unsigned*)&bs[(n0 + g) * BSTRH + kb + 2 * t];
                b[nt][1] = *(const unsigned*)&bs[(n0 + g) * BSTRH + kb + 2 * t + 8];
            }
            #pragma unroll
            for (int mt = 0; mt < 2; mt++)
                #pragma unroll
                for (int nt = 0; nt < 4; nt++)
                    asm volatile(
                        "mma.sync.aligned.m16n8k16.row.col.f32.f16.f16.f32 "
                        "{%0,%1,%2,%3},{%4,%5,%6,%7},{%8,%9},{%0,%1,%2,%3};"
                        : "+f"(c[mt][nt][0]), "+f"(c[mt][nt][1]),
                          "+f"(c[mt][nt][2]), "+f"(c[mt][nt][3])
                        : "r"(a[mt][0]), "r"(a[mt][1]), "r"(a[mt][2]), "r"(a[mt][3]),
                          "r"(b[nt][0]), "r"(b[nt][1]));
        }
        __syncthreads();
    }

    if (C16) {
        #pragma unroll
        for (int mt = 0; mt < 2; mt++) {
            int rr = row0 + wm * 32 + mt * 16 + g;
            #pragma unroll
            for (int nt = 0; nt < 4; nt++) {
                int cc = col0 + wn * 32 + nt * 8 + 2 * t;
                if (rr < M && cc + 1 < N)
                    *(__half2*)(C16 + (size_t)rr * N + cc) =
                        __floats2half2_rn(c[mt][nt][0], c[mt][nt][1]);
                if (rr + 8 < M && cc + 1 < N)
                    *(__half2*)(C16 + (size_t)(rr + 8) * N + cc) =
                        __floats2half2_rn(c[mt][nt][2], c[mt][nt][3]);
            }
        }
    } else {
        #pragma unroll
        for (int mt = 0; mt < 2; mt++) {
            int rr = row0 + wm * 32 + mt * 16 + g;
            #pragma unroll
            for (int nt = 0; nt < 4; nt++) {
                int cc = col0 + wn * 32 + nt * 8 + 2 * t;
                if (rr < M) {
                    if (cc     < N) C[(size_t)rr * N + cc]     = c[mt][nt][0];
                    if (cc + 1 < N) C[(size_t)rr * N + cc + 1] = c[mt][nt][1];
                }
                if (rr + 8 < M) {
                    if (cc     < N) C[(size_t)(rr + 8) * N + cc]     = c[mt][nt][2];
                    if (cc + 1 < N) C[(size_t)(rr + 8) * N + cc + 1] = c[mt][nt][3];
                }
            }
        }
    }
}

// ---------------- el/er for 8-head layers (fp16 features): warp per node + global-max ----------------
__global__ void elr8_k(const __half* __restrict__ h16, const float* __restrict__ al,
                       const float* __restrict__ ar) {
    __shared__ float sm_el[8], sm_er[8];
    int warp = threadIdx.x >> 5;
    int w = blockIdx.x * 8 + warp;
    int lane = threadIdx.x & 31;
    uint4 hv = *(const uint4*)(h16 + (size_t)w * HF + lane * 8);
    float2 f0 = __half22float2(*(__half2*)&hv.x);
    float2 f1 = __half22float2(*(__half2*)&hv.y);
    float2 f2 = __half22float2(*(__half2*)&hv.z);
    float2 f3 = __half22float2(*(__half2*)&hv.w);
    const float4* alp = (const float4*)(al + lane * 8);
    const float4* arp = (const float4*)(ar + lane * 8);
    float4 l0 = alp[0], l1 = alp[1], r0 = arp[0], r1 = arp[1];
    float pel = f0.x*l0.x + f0.y*l0.y + f1.x*l0.z + f1.y*l0.w
              + f2.x*l1.x + f2.y*l1.y + f3.x*l1.z + f3.y*l1.w;
    float per = f0.x*r0.x + f0.y*r0.y + f1.x*r0.z + f1.y*r0.w
              + f2.x*r1.x + f2.y*r1.y + f3.x*r1.z + f3.y*r1.w;
    pel += __shfl_xor_sync(0xffffffffu, pel, 1);
    pel += __shfl_xor_sync(0xffffffffu, pel, 2);
    per += __shfl_xor_sync(0xffffffffu, per, 1);
    per += __shfl_xor_sync(0xffffffffu, per, 2);
    if ((lane & 3) == 0) {
        g_el[w * HEADS + (lane >> 2)] = pel;
        g_er[w * HEADS + (lane >> 2)] = per;
    }
    float mel = pel, mer = per;
    #pragma unroll
    for (int d = 4; d <= 16; d <<= 1) {
        mel = fmaxf(mel, __shfl_xor_sync(0xffffffffu, mel, d));
        mer = fmaxf(mer, __shfl_xor_sync(0xffffffffu, mer, d));
    }
    if (lane == 0) { sm_el[warp] = mel; sm_er[warp] = mer; }
    __syncthreads();
    if (warp == 0) {
        float vel = (lane < 8) ? sm_el[lane] : -INFINITY;
        float ver = (lane < 8) ? sm_er[lane] : -INFINITY;
        #pragma unroll
        for (int d = 1; d <= 4; d <<= 1) {
            vel = fmaxf(vel, __shfl_xor_sync(0xffffffffu, vel, d));
            ver = fmaxf(ver, __shfl_xor_sync(0xffffffffu, ver, d));
        }
        if (lane == 0) {
            atomicMax(&g_mx[0], fenc(vel));
            atomicMax(&g_mx[1], fenc(ver));
        }
    }
}

// ---------------- 8-head aggregation: warp per dst, single pass, uint4 fp16 gather ----------------
__global__ void agg8_k(const __half* __restrict__ h16, __half* __restrict__ out, int do_elu) {
    int w = (blockIdx.x * blockDim.x + threadIdx.x) >> 5;
    int lane = threadIdx.x & 31;
    if (w >= N_NODES) return;
    int head = lane >> 2;
    float M = lrelu(fdec(g_mx[0]) + fdec(g_mx[1]));   // global upper bound on all logits
    float erd = g_er[w * HEADS + head];
    int b = g_off[w], e = g_off[w + 1];
    float a0=0,a1=0,a2=0,a3=0,a4=0,a5=0,a6=0,a7=0, ss=0;
    for (int i = b; i < e; i++) {
        int s = g_ssrc[i];
        float ex = __expf(lrelu(g_el[s * HEADS + head] + erd) - M);
        ss += ex;
        uint4 hv = *(const uint4*)(h16 + (size_t)s * HF + lane * 8);
        float2 f0 = __half22float2(*(__half2*)&hv.x);
        float2 f1 = __half22float2(*(__half2*)&hv.y);
        float2 f2 = __half22float2(*(__half2*)&hv.z);
        float2 f3 = __half22float2(*(__half2*)&hv.w);
        a0 += ex*f0.x; a1 += ex*f0.y; a2 += ex*f1.x; a3 += ex*f1.y;
        a4 += ex*f2.x; a5 += ex*f2.y; a6 += ex*f3.x; a7 += ex*f3.y;
    }
    float inv = 1.f / (ss + 1e-16f);
    float r[8] = {a0*inv, a1*inv, a2*inv, a3*inv, a4*inv, a5*inv, a6*inv, a7*inv};
    if (do_elu) {
        #pragma unroll
        for (int k = 0; k < 8; k++) r[k] = r[k] > 0.f ? r[k] : expm1f(r[k]);
    }
    __half2 h01 = __floats2half2_rn(r[0], r[1]);
    __half2 h23 = __floats2half2_rn(r[2], r[3]);
    __half2 h45 = __floats2half2_rn(r[4], r[5]);
    __half2 h67 = __floats2half2_rn(r[6], r[7]);
    uint4 pk;
    pk.x = *(unsigned*)&h01; pk.y = *(unsigned*)&h23;
    pk.z = *(unsigned*)&h45; pk.w = *(unsigned*)&h67;
    *(uint4*)(out + (size_t)w * HF + lane * 8) = pk;
}

// ---------------- output layer el/er (H=1, F=40): warp per node + global-max reduce ----------------
__global__ void elro_k(const float* __restrict__ h, const float* __restrict__ alo,
                       const float* __restrict__ aro) {
    __shared__ float sm_el[8], sm_er[8];
    int warp = threadIdx.x >> 5;
    int w = blockIdx.x * 8 + warp;
    int lane = threadIdx.x & 31;
    float v1 = h[(size_t)w * N_CLASSES + lane];
    float v2 = (lane < 8) ? h[(size_t)w * N_CLASSES + 32 + lane] : 0.f;
    float pel = v1 * alo[lane] + ((lane < 8) ? v2 * alo[32 + lane] : 0.f);
    float per = v1 * aro[lane] + ((lane < 8) ? v2 * aro[32 + lane] : 0.f);
    #pragma unroll
    for (int d = 16; d >= 1; d >>= 1) {
        pel += __shfl_xor_sync(0xffffffffu, pel, d);
        per += __shfl_xor_sync(0xffffffffu, per, d);
    }
    if (lane == 0) { g_el[w] = pel; g_er[w] = per; sm_el[warp] = pel; sm_er[warp] = per; }
    __syncthreads();
    if (warp == 0) {
        float vel = (lane < 8) ? sm_el[lane] : -INFINITY;
        float ver = (lane < 8) ? sm_er[lane] : -INFINITY;
        #pragma unroll
        for (int d = 1; d <= 4; d <<= 1) {
            vel = fmaxf(vel, __shfl_xor_sync(0xffffffffu, vel, d));
            ver = fmaxf(ver, __shfl_xor_sync(0xffffffffu, ver, d));
        }
        if (lane == 0) {
            atomicMax(&g_mx[0], fenc(vel));
            atomicMax(&g_mx[1], fenc(ver));
        }
    }
}

// ---------------- output aggregation + fused log_softmax: warp per dst, single pass ----------------
__global__ void agg1ls_k(const float* __restrict__ h, float* __restrict__ out) {
    int w = (blockIdx.x * blockDim.x + threadIdx.x) >> 5;
    int lane = threadIdx.x & 31;
    if (w >= N_NODES) return;
    float M = lrelu(fdec(g_mx[0]) + fdec(g_mx[1]));
    float erd = g_er[w];
    int b = g_off[w], e = g_off[w + 1];
    float a0 = 0, a1 = 0, ss = 0;
    for (int i = b; i < e; i++) {
        int s = g_ssrc[i];
        float ex = __expf(lrelu(g_el[s] + erd) - M);
        ss += ex;
        a0 += ex * h[(size_t)s * N_CLASSES + lane];
        if (lane < 8) a1 += ex * h[(size_t)s * N_CLASSES + 32 + lane];
    }
    float inv = 1.f / (ss + 1e-16f);
    float v1 = a0 * inv;
    float v2 = (lane < 8) ? a1 * inv : -INFINITY;
    float m = fmaxf(v1, v2);
    #pragma unroll
    for (int d = 16; d >= 1; d >>= 1) m = fmaxf(m, __shfl_xor_sync(0xffffffffu, m, d));
    float s = expf(v1 - m) + ((lane < 8) ? expf(v2 - m) : 0.f);
    #pragma unroll
    for (int d = 16; d >= 1; d >>= 1) s += __shfl_xor_sync(0xffffffffu, s, d);
    float ls = logf(s) + m;
    out[(size_t)w * N_CLASSES + lane] = v1 - ls;
    if (lane < 8) out[(size_t)w * N_CLASSES + 32 + lane] = v2 - ls;
}

// ---------------- host launcher ----------------
static inline int cdiv(int a, int b) { return (a + b - 1) / b; }

extern "C" void kernel_launch(void* const* d_in, const int* in_sizes, int n_in,
                              void* d_out, int out_size) {
    const float* x   = (const float*)d_in[0];
    const int*   src = (const int*)d_in[1];
    const int*   dst = (const int*)d_in[2];
    const float* W1  = (const float*)d_in[3];
    const float* al1 = (const float*)d_in[4];
    const float* ar1 = (const float*)d_in[5];
    const float* W2  = (const float*)d_in[6];
    const float* al2 = (const float*)d_in[7];
    const float* ar2 = (const float*)d_in[8];
    const float* Wo  = (const float*)d_in[9];
    const float* alo = (const float*)d_in[10];
    const float* aro = (const float*)d_in[11];
    float* out = (float*)d_out;

    void *pH16, *pQh, *pX16, *pW1T, *pW2T, *pWoT, *pO1;
    cudaGetSymbolAddress(&pH16, g_h16);
    cudaGetSymbolAddress(&pQh, g_Qh);
    cudaGetSymbolAddress(&pX16, g_x16);
    cudaGetSymbolAddress(&pW1T, g_W1T);
    cudaGetSymbolAddress(&pW2T, g_W2T);
    cudaGetSymbolAddress(&pWoT, g_WoT);
    cudaGetSymbolAddress(&pO1, g_o1);

    // conversions (cvtA also zeroes g_cnt/g_cur for the CSR build)
    cvtA_k<<<cdiv(N_NODES * IN_F, 256), 256>>>(x, (__half*)pX16, N_NODES * IN_F);
    cvtBT_k<<<cdiv(IN_F * HF, 256), 256>>>(W1, (__half*)pW1T, IN_F, HF, HF);
    cvtBT_k<<<cdiv(HF * HF, 256), 256>>>(W2, (__half*)pW2T, HF, HF, HF);
    cvtBT_k<<<cdiv(HF * 64, 256), 256>>>(Wo, (__half*)pWoT, HF, N_CLASSES, 64);

    // CSR build (by dst)
    int eb = cdiv(N_EDGES, 256);
    hist_k<<<eb, 256>>>(dst);
    scan_k<<<1, 1024>>>();
    scatter_k<<<eb, 256>>>(src, dst);

    int nwb = N_NODES * 32 / 256;            // 6250 blocks, 8 warps each
    dim3 g1(cdiv(HF, TBN), cdiv(N_NODES, TBM));      // 4 x 391
    dim3 g3(1, cdiv(N_NODES, TBM));                   // N=40 -> 1 col tile

    // layer 1: fp16 GEMM -> fp16 features (also resets g_mx)
    gemm_h<<<g1, 256>>>((const __half*)pX16, (const __half*)pW1T, nullptr, (__half*)pH16,
                        N_NODES, HF, IN_F, 1);
    elr8_k<<<nwb, 256>>>((const __half*)pH16, al1, ar1);
    agg8_k<<<nwb, 256>>>((const __half*)pH16, (__half*)pQh, 1);

    // layer 2
    gemm_h<<<g1, 256>>>((const __half*)pQh, (const __half*)pW2T, nullptr, (__half*)pH16,
                        N_NODES, HF, HF, 1);
    elr8_k<<<nwb, 256>>>((const __half*)pH16, al2, ar2);
    agg8_k<<<nwb, 256>>>((const __half*)pH16, (__half*)pQh, 1);

    // output layer: fp16 GEMM -> fp32 logits; rest fp32 (GEMM resets g_mx)
    gemm_h<<<g3, 256>>>((const __half*)pQh, (const __half*)pWoT, (float*)pO1, (__half*)nullptr,
                        N_NODES, N_CLASSES, HF, 1);
    elro_k<<<nwb, 256>>>((const float*)pO1, alo, aro);
    agg1ls_k<<<nwb, 256>>>((const float*)pO1, out);
}

// round 16
// speedup vs baseline: 1.5106x; 1.0175x over previous
#include <cuda_runtime.h>
#include <cuda_fp16.h>
#include <math.h>

#define N_NODES 50000
#define N_EDGES 800000
#define IN_F    128
#define HID     32
#define HEADS   8
#define HF      256          // HEADS*HID
#define N_CLASSES 40
#define NEG_SLOPE 0.2f

// ---------------- scratch (device globals; no allocation allowed) ----------------
__device__ __half g_h16[N_NODES * HF];        // fp16 projected features P (layers 1-2)
__device__ __half g_Qh[N_NODES * HF];         // fp16 aggregated features Q (GEMM A input)
__device__ __half g_x16[N_NODES * IN_F];      // fp16 copy of input x
__device__ __half g_W1T[HF * IN_F];           // W1^T fp16 [n][k]
__device__ __half g_W2T[HF * HF];             // W2^T fp16 [n][k]
__device__ __half g_WoT[64 * HF];             // Wo^T fp16 [n][k], padded 40->64 rows
__device__ __half g_o1h[N_NODES * N_CLASSES]; // output-layer projection (fp16)
__device__ float  g_el[N_NODES * HEADS];
__device__ float  g_er[N_NODES * HEADS];
__device__ int    g_cnt[N_NODES];
__device__ int    g_cur[N_NODES];
__device__ int    g_off[N_NODES + 1];
__device__ int    g_ssrc[N_EDGES];
__device__ unsigned g_mx[2];                  // encoded global max of el / er (per layer)

__device__ __forceinline__ float lrelu(float v) { return v > 0.f ? v : NEG_SLOPE * v; }

// order-preserving float<->uint encode for atomicMax
__device__ __forceinline__ unsigned fenc(float f) {
    unsigned u = __float_as_uint(f);
    return (u & 0x80000000u) ? ~u : (u | 0x80000000u);
}
__device__ __forceinline__ float fdec(unsigned u) {
    return (u & 0x80000000u) ? __uint_as_float(u & 0x7fffffffu) : __uint_as_float(~u);
}

// ---------------- converters ----------------
// also zeroes g_cnt/g_cur (runs before hist_k)
__global__ void cvtA_k(const float* __restrict__ src, __half* __restrict__ dst, int n) {
    int i = blockIdx.x * blockDim.x + threadIdx.x;
    if (i < n) dst[i] = __float2half_rn(src[i]);
    if (i < N_NODES) { g_cnt[i] = 0; g_cur[i] = 0; }
}

// fused transpose+convert of all three weight matrices into g_W1T/g_W2T/g_WoT
#define W1T_ELEMS (HF * IN_F)          // 32768
#define W2T_ELEMS (HF * HF)            // 65536
#define WOT_ELEMS (64 * HF)            // 16384
#define WALL_ELEMS (W1T_ELEMS + W2T_ELEMS + WOT_ELEMS)
__global__ void cvtW_k(const float* __restrict__ W1, const float* __restrict__ W2,
                       const float* __restrict__ Wo) {
    int i = blockIdx.x * blockDim.x + threadIdx.x;
    if (i >= WALL_ELEMS) return;
    if (i < W1T_ELEMS) {
        int n = i / IN_F, k = i % IN_F;                   // BT[n][k], K=IN_F, N=HF
        g_W1T[i] = __float2half_rn(W1[k * HF + n]);
    } else if (i < W1T_ELEMS + W2T_ELEMS) {
        int j = i - W1T_ELEMS;
        int n = j / HF, k = j % HF;                       // K=HF, N=HF
        g_W2T[j] = __float2half_rn(W2[k * HF + n]);
    } else {
        int j = i - W1T_ELEMS - W2T_ELEMS;
        int n = j / HF, k = j % HF;                       // K=HF, NBT=64, N=N_CLASSES
        g_WoT[j] = __float2half_rn((n < N_CLASSES) ? Wo[k * N_CLASSES + n] : 0.f);
    }
}

// ---------------- CSR build: histogram -> scan -> scatter ----------------
__global__ void hist_k(const int* __restrict__ dst) {
    int i = blockIdx.x * blockDim.x + threadIdx.x;
    if (i < N_EDGES) atomicAdd(&g_cnt[dst[i]], 1);
}

__global__ void scan_k() {   // one block, 1024 threads
    __shared__ int sh[1024];
    int t = threadIdx.x;
    const int n = N_NODES;
    const int chunk = (n + 1023) / 1024;
    int lo = t * chunk;
    int hi = lo + chunk; if (hi > n) hi = n;
    int s = 0;
    for (int i = lo; i < hi; i++) s += g_cnt[i];
    sh[t] = s;
    __syncthreads();
    int own = s;
    for (int d = 1; d < 1024; d <<= 1) {
        int v = (t >= d) ? sh[t - d] : 0;
        __syncthreads();
        sh[t] += v;
        __syncthreads();
    }
    int base = sh[t] - own;
    for (int i = lo; i < hi; i++) { g_off[i] = base; base += g_cnt[i]; }
    if (t == 1023) g_off[n] = sh[1023];
}

__global__ void scatter_k(const int* __restrict__ src, const int* __restrict__ dst) {
    int i = blockIdx.x * blockDim.x + threadIdx.x;
    if (i < N_EDGES) {
        int d = dst[i];
        int pos = atomicAdd(&g_cur[d], 1);
        g_ssrc[g_off[d] + pos] = src[i];
    }
}

// ---------------- fp16 tensor-core GEMM (m16n8k16), cp.async double buffered ----------------
// A fp16 row-major [M,K]; BT fp16 [NBT][K] (B transposed, rows padded).
// Writes fp16 C16[M,N] (bounds-checked pair writes).
// reset_mx: thread(0,0) zeroes g_mx (consumed by elr/elro which launch after this kernel).
__device__ __forceinline__ void cp_async16(unsigned smem_addr, const void* gptr) {
    asm volatile("cp.async.cg.shared.global [%0], [%1], 16;\n" :: "r"(smem_addr), "l"(gptr));
}
__device__ __forceinline__ void cp_commit() { asm volatile("cp.async.commit_group;\n" ::: "memory"); }
__device__ __forceinline__ void cp_wait1() { asm volatile("cp.async.wait_group 1;\n" ::: "memory"); }
__device__ __forceinline__ void cp_wait0() { asm volatile("cp.async.wait_group 0;\n" ::: "memory"); }

#define TBM 128
#define TBN 64
#define TBK 32        // halves per k-block
#define ASTRH 40      // A smem row stride in halves
#define BSTRH 40      // B smem row stride in halves

__global__ __launch_bounds__(256) void gemm_h(const __half* __restrict__ A,
                                              const __half* __restrict__ BT,
                                              __half* __restrict__ C16,
                                              int M, int N, int K, int reset_mx) {
    __shared__ __half As[2][TBM * ASTRH];
    __shared__ __half Bs[2][TBN * BSTRH];
    int tid = threadIdx.x;
    if (reset_mx && tid == 0 && blockIdx.x == 0 && blockIdx.y == 0) {
        g_mx[0] = 0u; g_mx[1] = 0u;
    }
    int lane = tid & 31, warp = tid >> 5;
    int wm = warp & 3, wn = warp >> 2;           // 4 (m) x 2 (n) warps
    int g = lane >> 2, t = lane & 3;
    int row0 = blockIdx.y * TBM, col0 = blockIdx.x * TBN;

    int ar = tid >> 2;          // 0..63
    int ac = (tid & 3) << 3;    // 0,8,16,24 halves
    unsigned as_base = (unsigned)__cvta_generic_to_shared(&As[0][0]);
    unsigned bs_base = (unsigned)__cvta_generic_to_shared(&Bs[0][0]);

    float c[2][4][4];
    #pragma unroll
    for (int i = 0; i < 2; i++)
        #pragma unroll
        for (int j = 0; j < 4; j++)
            #pragma unroll
            for (int k = 0; k < 4; k++) c[i][j][k] = 0.f;

    int nk = K / TBK;

    auto load_tile = [&](int buf, int k0) {
        #pragma unroll
        for (int i = 0; i < 2; i++) {
            int r = ar + i * 64;
            int gr = row0 + r;
            const __half* sp = (gr < M) ? (A + (size_t)gr * K + k0 + ac) : A;
            cp_async16(as_base + (buf * TBM * ASTRH + r * ASTRH + ac) * 2, sp);
        }
        {
            const __half* sp = BT + (size_t)(col0 + ar) * K + k0 + ac;
            cp_async16(bs_base + (buf * TBN * BSTRH + ar * BSTRH + ac) * 2, sp);
        }
    };

    load_tile(0, 0);
    cp_commit();

    for (int kt = 0; kt < nk; kt++) {
        int buf = kt & 1;
        if (kt + 1 < nk) { load_tile(buf ^ 1, (kt + 1) * TBK); cp_commit(); cp_wait1(); }
        else cp_wait0();
        __syncthreads();

        const __half* as = &As[buf][0];
        const __half* bs = &Bs[buf][0];
        #pragma unroll
        for (int ks = 0; ks < 2; ks++) {
            int kb = ks * 16;
            unsigned a[2][4], b[4][2];
            #pragma unroll
            for (int mt = 0; mt < 2; mt++) {
                int m0 = wm * 32 + mt * 16;
                a[mt][0] = *(const unsigned*)&as[(m0 + g)     * ASTRH + kb + 2 * t];
                a[mt][1] = *(const unsigned*)&as[(m0 + g + 8) * ASTRH + kb + 2 * t];
                a[mt][2] = *(const unsigned*)&as[(m0 + g)     * ASTRH + kb + 2 * t + 8];
                a[mt][3] = *(const unsigned*)&as[(m0 + g + 8) * ASTRH + kb + 2 * t + 8];
            }
            #pragma unroll
            for (int nt = 0; nt < 4; nt++) {
                int n0 = wn * 32 + nt * 8;
                b[nt][0] = *(const unsigned*)&bs[(n0 + g) * BSTRH + kb + 2 * t];
                b[nt][1] = *(const unsigned*)&bs[(n0 + g) * BSTRH + kb + 2 * t + 8];
            }
            #pragma unroll
            for (int mt = 0; mt < 2; mt++)
                #pragma unroll
                for (int nt = 0; nt < 4; nt++)
                    asm volatile(
                        "mma.sync.aligned.m16n8k16.row.col.f32.f16.f16.f32 "
                        "{%0,%1,%2,%3},{%4,%5,%6,%7},{%8,%9},{%0,%1,%2,%3};"
                        : "+f"(c[mt][nt][0]), "+f"(c[mt][nt][1]),
                          "+f"(c[mt][nt][2]), "+f"(c[mt][nt][3])
                        : "r"(a[mt][0]), "r"(a[mt][1]), "r"(a[mt][2]), "r"(a[mt][3]),
                          "r"(b[nt][0]), "r"(b[nt][1]));
        }
        __syncthreads();
    }

    #pragma unroll
    for (int mt = 0; mt < 2; mt++) {
        int rr = row0 + wm * 32 + mt * 16 + g;
        #pragma unroll
        for (int nt = 0; nt < 4; nt++) {
            int cc = col0 + wn * 32 + nt * 8 + 2 * t;
            if (rr < M && cc + 1 < N)
                *(__half2*)(C16 + (size_t)rr * N + cc) =
                    __floats2half2_rn(c[mt][nt][0], c[mt][nt][1]);
            if (rr + 8 < M && cc + 1 < N)
                *(__half2*)(C16 + (size_t)(rr + 8) * N + cc) =
                    __floats2half2_rn(c[mt][nt][2], c[mt][nt][3]);
        }
    }
}

// ---------------- el/er for 8-head layers (fp16 features): warp per node + global-max ----------------
__global__ void elr8_k(const __half* __restrict__ h16, const float* __restrict__ al,
                       const float* __restrict__ ar) {
    __shared__ float sm_el[8], sm_er[8];
    int warp = threadIdx.x >> 5;
    int w = blockIdx.x * 8 + warp;
    int lane = threadIdx.x & 31;
    uint4 hv = *(const uint4*)(h16 + (size_t)w * HF + lane * 8);
    float2 f0 = __half22float2(*(__half2*)&hv.x);
    float2 f1 = __half22float2(*(__half2*)&hv.y);
    float2 f2 = __half22float2(*(__half2*)&hv.z);
    float2 f3 = __half22float2(*(__half2*)&hv.w);
    const float4* alp = (const float4*)(al + lane * 8);
    const float4* arp = (const float4*)(ar + lane * 8);
    float4 l0 = alp[0], l1 = alp[1], r0 = arp[0], r1 = arp[1];
    float pel = f0.x*l0.x + f0.y*l0.y + f1.x*l0.z + f1.y*l0.w
              + f2.x*l1.x + f2.y*l1.y + f3.x*l1.z + f3.y*l1.w;
    float per = f0.x*r0.x + f0.y*r0.y + f1.x*r0.z + f1.y*r0.w
              + f2.x*r1.x + f2.y*r1.y + f3.x*r1.z + f3.y*r1.w;
    pel += __shfl_xor_sync(0xffffffffu, pel, 1);
    pel += __shfl_xor_sync(0xffffffffu, pel, 2);
    per += __shfl_xor_sync(0xffffffffu, per, 1);
    per += __shfl_xor_sync(0xffffffffu, per, 2);
    if ((lane & 3) == 0) {
        g_el[w * HEADS + (lane >> 2)] = pel;
        g_er[w * HEADS + (lane >> 2)] = per;
    }
    float mel = pel, mer = per;
    #pragma unroll
    for (int d = 4; d <= 16; d <<= 1) {
        mel = fmaxf(mel, __shfl_xor_sync(0xffffffffu, mel, d));
        mer = fmaxf(mer, __shfl_xor_sync(0xffffffffu, mer, d));
    }
    if (lane == 0) { sm_el[warp] = mel; sm_er[warp] = mer; }
    __syncthreads();
    if (warp == 0) {
        float vel = (lane < 8) ? sm_el[lane] : -INFINITY;
        float ver = (lane < 8) ? sm_er[lane] : -INFINITY;
        #pragma unroll
        for (int d = 1; d <= 4; d <<= 1) {
            vel = fmaxf(vel, __shfl_xor_sync(0xffffffffu, vel, d));
            ver = fmaxf(ver, __shfl_xor_sync(0xffffffffu, ver, d));
        }
        if (lane == 0) {
            atomicMax(&g_mx[0], fenc(vel));
            atomicMax(&g_mx[1], fenc(ver));
        }
    }
}

// ---------------- 8-head aggregation: warp per dst, single pass, uint4 fp16 gather ----------------
__global__ void agg8_k(const __half* __restrict__ h16, __half* __restrict__ out, int do_elu) {
    int w = (blockIdx.x * blockDim.x + threadIdx.x) >> 5;
    int lane = threadIdx.x & 31;
    if (w >= N_NODES) return;
    int head = lane >> 2;
    float M = lrelu(fdec(g_mx[0]) + fdec(g_mx[1]));   // global upper bound on all logits
    float erd = g_er[w * HEADS + head];
    int b = g_off[w], e = g_off[w + 1];
    float a0=0,a1=0,a2=0,a3=0,a4=0,a5=0,a6=0,a7=0, ss=0;
    for (int i = b; i < e; i++) {
        int s = g_ssrc[i];
        float ex = __expf(lrelu(g_el[s * HEADS + head] + erd) - M);
        ss += ex;
        uint4 hv = *(const uint4*)(h16 + (size_t)s * HF + lane * 8);
        float2 f0 = __half22float2(*(__half2*)&hv.x);
        float2 f1 = __half22float2(*(__half2*)&hv.y);
        float2 f2 = __half22float2(*(__half2*)&hv.z);
        float2 f3 = __half22float2(*(__half2*)&hv.w);
        a0 += ex*f0.x; a1 += ex*f0.y; a2 += ex*f1.x; a3 += ex*f1.y;
        a4 += ex*f2.x; a5 += ex*f2.y; a6 += ex*f3.x; a7 += ex*f3.y;
    }
    float inv = 1.f / (ss + 1e-16f);
    float r[8] = {a0*inv, a1*inv, a2*inv, a3*inv, a4*inv, a5*inv, a6*inv, a7*inv};
    if (do_elu) {
        #pragma unroll
        for (int k = 0; k < 8; k++) r[k] = r[k] > 0.f ? r[k] : expm1f(r[k]);
    }
    __half2 h01 = __floats2half2_rn(r[0], r[1]);
    __half2 h23 = __floats2half2_rn(r[2], r[3]);
    __half2 h45 = __floats2half2_rn(r[4], r[5]);
    __half2 h67 = __floats2half2_rn(r[6], r[7]);
    uint4 pk;
    pk.x = *(unsigned*)&h01; pk.y = *(unsigned*)&h23;
    pk.z = *(unsigned*)&h45; pk.w = *(unsigned*)&h67;
    *(uint4*)(out + (size_t)w * HF + lane * 8) = pk;
}

// ---------------- output layer el/er (H=1, F=40, fp16 feats): warp per node + global-max ----------------
__global__ void elro_k(const __half* __restrict__ h, const float* __restrict__ alo,
                       const float* __restrict__ aro) {
    __shared__ float sm_el[8], sm_er[8];
    int warp = threadIdx.x >> 5;
    int w = blockIdx.x * 8 + warp;
    int lane = threadIdx.x & 31;
    float v1 = __half2float(h[(size_t)w * N_CLASSES + lane]);
    float v2 = (lane < 8) ? __half2float(h[(size_t)w * N_CLASSES + 32 + lane]) : 0.f;
    float pel = v1 * alo[lane] + ((lane < 8) ? v2 * alo[32 + lane] : 0.f);
    float per = v1 * aro[lane] + ((lane < 8) ? v2 * aro[32 + lane] : 0.f);
    #pragma unroll
    for (int d = 16; d >= 1; d >>= 1) {
        pel += __shfl_xor_sync(0xffffffffu, pel, d);
        per += __shfl_xor_sync(0xffffffffu, per, d);
    }
    if (lane == 0) { g_el[w] = pel; g_er[w] = per; sm_el[warp] = pel; sm_er[warp] = per; }
    __syncthreads();
    if (warp == 0) {
        float vel = (lane < 8) ? sm_el[lane] : -INFINITY;
        float ver = (lane < 8) ? sm_er[lane] : -INFINITY;
        #pragma unroll
        for (int d = 1; d <= 4; d <<= 1) {
            vel = fmaxf(vel, __shfl_xor_sync(0xffffffffu, vel, d));
            ver = fmaxf(ver, __shfl_xor_sync(0xffffffffu, ver, d));
        }
        if (lane == 0) {
            atomicMax(&g_mx[0], fenc(vel));
            atomicMax(&g_mx[1], fenc(ver));
        }
    }
}

// ---------------- output aggregation + fused log_softmax (fp16 feats): warp per dst ----------------
__global__ void agg1ls_k(const __half* __restrict__ h, float* __restrict__ out) {
    int w = (blockIdx.x * blockDim.x + threadIdx.x) >> 5;
    int lane = threadIdx.x & 31;
    if (w >= N_NODES) return;
    float M = lrelu(fdec(g_mx[0]) + fdec(g_mx[1]));
    float erd = g_er[w];
    int b = g_off[w], e = g_off[w + 1];
    float a0 = 0, a1 = 0, ss = 0;
    for (int i = b; i < e; i++) {
        int s = g_ssrc[i];
        float ex = __expf(lrelu(g_el[s] + erd) - M);
        ss += ex;
        a0 += ex * __half2float(h[(size_t)s * N_CLASSES + lane]);
        if (lane < 8) a1 += ex * __half2float(h[(size_t)s * N_CLASSES + 32 + lane]);
    }
    float inv = 1.f / (ss + 1e-16f);
    float v1 = a0 * inv;
    float v2 = (lane < 8) ? a1 * inv : -INFINITY;
    float m = fmaxf(v1, v2);
    #pragma unroll
    for (int d = 16; d >= 1; d >>= 1) m = fmaxf(m, __shfl_xor_sync(0xffffffffu, m, d));
    float s = expf(v1 - m) + ((lane < 8) ? expf(v2 - m) : 0.f);
    #pragma unroll
    for (int d = 16; d >= 1; d >>= 1) s += __shfl_xor_sync(0xffffffffu, s, d);
    float ls = logf(s) + m;
    out[(size_t)w * N_CLASSES + lane] = v1 - ls;
    if (lane < 8) out[(size_t)w * N_CLASSES + 32 + lane] = v2 - ls;
}

// ---------------- host launcher ----------------
static inline int cdiv(int a, int b) { return (a + b - 1) / b; }

extern "C" void kernel_launch(void* const* d_in, const int* in_sizes, int n_in,
                              void* d_out, int out_size) {
    const float* x   = (const float*)d_in[0];
    const int*   src = (const int*)d_in[1];
    const int*   dst = (const int*)d_in[2];
    const float* W1  = (const float*)d_in[3];
    const float* al1 = (const float*)d_in[4];
    const float* ar1 = (const float*)d_in[5];
    const float* W2  = (const float*)d_in[6];
    const float* al2 = (const float*)d_in[7];
    const float* ar2 = (const float*)d_in[8];
    const float* Wo  = (const float*)d_in[9];
    const float* alo = (const float*)d_in[10];
    const float* aro = (const float*)d_in[11];
    float* out = (float*)d_out;

    void *pH16, *pQh, *pX16, *pW1T, *pW2T, *pWoT, *pO1h;
    cudaGetSymbolAddress(&pH16, g_h16);
    cudaGetSymbolAddress(&pQh, g_Qh);
    cudaGetSymbolAddress(&pX16, g_x16);
    cudaGetSymbolAddress(&pW1T, g_W1T);
    cudaGetSymbolAddress(&pW2T, g_W2T);
    cudaGetSymbolAddress(&pWoT, g_WoT);
    cudaGetSymbolAddress(&pO1h, g_o1h);

    // conversions (cvtA also zeroes g_cnt/g_cur; cvtW fuses all 3 weight transposes)
    cvtA_k<<<cdiv(N_NODES * IN_F, 256), 256>>>(x, (__half*)pX16, N_NODES * IN_F);
    cvtW_k<<<cdiv(WALL_ELEMS, 256), 256>>>(W1, W2, Wo);

    // CSR build (by dst)
    int eb = cdiv(N_EDGES, 256);
    hist_k<<<eb, 256>>>(dst);
    scan_k<<<1, 1024>>>();
    scatter_k<<<eb, 256>>>(src, dst);

    int nwb = N_NODES * 32 / 256;            // 6250 blocks, 8 warps each
    dim3 g1(cdiv(HF, TBN), cdiv(N_NODES, TBM));      // 4 x 391
    dim3 g3(1, cdiv(N_NODES, TBM));                   // N=40 -> 1 col tile

    // layer 1: fp16 GEMM -> fp16 features (also resets g_mx)
    gemm_h<<<g1, 256>>>((const __half*)pX16, (const __half*)pW1T, (__half*)pH16,
                        N_NODES, HF, IN_F, 1);
    elr8_k<<<nwb, 256>>>((const __half*)pH16, al1, ar1);
    agg8_k<<<nwb, 256>>>((const __half*)pH16, (__half*)pQh, 1);

    // layer 2
    gemm_h<<<g1, 256>>>((const __half*)pQh, (const __half*)pW2T, (__half*)pH16,
                        N_NODES, HF, HF, 1);
    elr8_k<<<nwb, 256>>>((const __half*)pH16, al2, ar2);
    agg8_k<<<nwb, 256>>>((const __half*)pH16, (__half*)pQh, 1);

    // output layer: fp16 GEMM -> fp16 logits; fp32 math downstream (GEMM resets g_mx)
    gemm_h<<<g3, 256>>>((const __half*)pQh, (const __half*)pWoT, (__half*)pO1h,
                        N_NODES, N_CLASSES, HF, 1);
    elro_k<<<nwb, 256>>>((const __half*)pO1h, alo, aro);
    agg1ls_k<<<nwb, 256>>>((const __half*)pO1h, out);
}

// round 17
// speedup vs baseline: 1.7071x; 1.1301x over previous
#include <cuda_runtime.h>
#include <cuda_fp16.h>
#include <math.h>

#define N_NODES 50000
#define N_EDGES 800000
#define IN_F    128
#define HID     32
#define HEADS   8
#define HF      256          // HEADS*HID
#define N_CLASSES 40
#define NEG_SLOPE 0.2f
#define SCAN_B  1024
#define NBLK    49           // cdiv(N_NODES, SCAN_B)

// ---------------- scratch (device globals; no allocation allowed) ----------------
__device__ __half g_h16[N_NODES * HF];        // fp16 projected features P (layers 1-2)
__device__ __half g_Qh[N_NODES * HF];         // fp16 aggregated features Q (GEMM A input)
__device__ __half g_x16[N_NODES * IN_F];      // fp16 copy of input x
__device__ __half g_W1T[HF * IN_F];           // W1^T fp16 [n][k]
__device__ __half g_W2T[HF * HF];             // W2^T fp16 [n][k]
__device__ __half g_WoT[64 * HF];             // Wo^T fp16 [n][k], padded 40->64 rows
__device__ __half g_o1h[N_NODES * N_CLASSES]; // output-layer projection (fp16)
__device__ float  g_el[N_NODES * HEADS];
__device__ float  g_er[N_NODES * HEADS];
__device__ int    g_cnt[N_NODES];
__device__ int    g_cur[N_NODES];
__device__ int    g_off[N_NODES + 1];
__device__ int    g_bsum[NBLK];
__device__ int    g_bpre[NBLK];
__device__ int    g_ssrc[N_EDGES];
__device__ unsigned g_mx[2];                  // encoded global max of el / er (per layer)

__device__ __forceinline__ float lrelu(float v) { return v > 0.f ? v : NEG_SLOPE * v; }

// order-preserving float<->uint encode for atomicMax
__device__ __forceinline__ unsigned fenc(float f) {
    unsigned u = __float_as_uint(f);
    return (u & 0x80000000u) ? ~u : (u | 0x80000000u);
}
__device__ __forceinline__ float fdec(unsigned u) {
    return (u & 0x80000000u) ? __uint_as_float(u & 0x7fffffffu) : __uint_as_float(~u);
}

// ---------------- converters ----------------
// also zeroes g_cnt/g_cur (runs before hist_k)
__global__ void cvtA_k(const float* __restrict__ src, __half* __restrict__ dst, int n) {
    int i = blockIdx.x * blockDim.x + threadIdx.x;
    if (i < n) dst[i] = __float2half_rn(src[i]);
    if (i < N_NODES) { g_cnt[i] = 0; g_cur[i] = 0; }
}

// fused transpose+convert of all three weight matrices into g_W1T/g_W2T/g_WoT
#define W1T_ELEMS (HF * IN_F)          // 32768
#define W2T_ELEMS (HF * HF)            // 65536
#define WOT_ELEMS (64 * HF)            // 16384
#define WALL_ELEMS (W1T_ELEMS + W2T_ELEMS + WOT_ELEMS)
__global__ void cvtW_k(const float* __restrict__ W1, const float* __restrict__ W2,
                       const float* __restrict__ Wo) {
    int i = blockIdx.x * blockDim.x + threadIdx.x;
    if (i >= WALL_ELEMS) return;
    if (i < W1T_ELEMS) {
        int n = i / IN_F, k = i % IN_F;                   // BT[n][k], K=IN_F, N=HF
        g_W1T[i] = __float2half_rn(W1[k * HF + n]);
    } else if (i < W1T_ELEMS + W2T_ELEMS) {
        int j = i - W1T_ELEMS;
        int n = j / HF, k = j % HF;                       // K=HF, N=HF
        g_W2T[j] = __float2half_rn(W2[k * HF + n]);
    } else {
        int j = i - W1T_ELEMS - W2T_ELEMS;
        int n = j / HF, k = j % HF;                       // K=HF, NBT=64, N=N_CLASSES
        g_WoT[j] = __float2half_rn((n < N_CLASSES) ? Wo[k * N_CLASSES + n] : 0.f);
    }
}

// ---------------- CSR build: histogram -> multi-block scan -> scatter ----------------
__global__ void hist_k(const int* __restrict__ dst) {
    int i = blockIdx.x * blockDim.x + threadIdx.x;
    if (i < N_EDGES) atomicAdd(&g_cnt[dst[i]], 1);
}

// phase 1: per-block exclusive scan of g_cnt -> g_off (block-local) + block totals
__global__ void scan1_k() {
    __shared__ int sh[SCAN_B];
    int b = blockIdx.x, t = threadIdx.x;
    int i = b * SCAN_B + t;
    int v = (i < N_NODES) ? g_cnt[i] : 0;
    sh[t] = v;
    __syncthreads();
    #pragma unroll
    for (int d = 1; d < SCAN_B; d <<= 1) {
        int x = (t >= d) ? sh[t - d] : 0;
        __syncthreads();
        sh[t] += x;
        __syncthreads();
    }
    if (i < N_NODES) g_off[i] = sh[t] - v;     // exclusive, block-local
    if (t == SCAN_B - 1) g_bsum[b] = sh[t];
}

// phase 2: scan the 49 block totals (1 small block)
__global__ void scan2_k() {
    __shared__ int sh[64];
    int t = threadIdx.x;
    int v = (t < NBLK) ? g_bsum[t] : 0;
    sh[t] = v;
    __syncthreads();
    #pragma unroll
    for (int d = 1; d < 64; d <<= 1) {
        int x = (t >= d) ? sh[t - d] : 0;
        __syncthreads();
        sh[t] += x;
        __syncthreads();
    }
    if (t < NBLK) g_bpre[t] = sh[t] - v;
    if (t == 63) g_off[N_NODES] = sh[63];
}

// phase 3: add block prefixes
__global__ void scan3_k() {
    int b = blockIdx.x, t = threadIdx.x;
    int i = b * SCAN_B + t;
    if (i < N_NODES) g_off[i] += g_bpre[b];
}

__global__ void scatter_k(const int* __restrict__ src, const int* __restrict__ dst) {
    int i = blockIdx.x * blockDim.x + threadIdx.x;
    if (i < N_EDGES) {
        int d = dst[i];
        int pos = atomicAdd(&g_cur[d], 1);
        g_ssrc[g_off[d] + pos] = src[i];
    }
}

// ---------------- fp16 tensor-core GEMM (m16n8k16), cp.async double buffered ----------------
// A fp16 row-major [M,K]; BT fp16 [NBT][K] (B transposed, rows padded).
// Writes fp16 C16[M,N] (bounds-checked pair writes).
// reset_mx: thread(0,0) zeroes g_mx (consumed by elr/elro which launch after this kernel).
__device__ __forceinline__ void cp_async16(unsigned smem_addr, const void* gptr) {
    asm volatile("cp.async.cg.shared.global [%0], [%1], 16;\n" :: "r"(smem_addr), "l"(gptr));
}
__device__ __forceinline__ void cp_commit() { asm volatile("cp.async.commit_group;\n" ::: "memory"); }
__device__ __forceinline__ void cp_wait1() { asm volatile("cp.async.wait_group 1;\n" ::: "memory"); }
__device__ __forceinline__ void cp_wait0() { asm volatile("cp.async.wait_group 0;\n" ::: "memory"); }

#define TBM 128
#define TBN 64
#define TBK 32        // halves per k-block
#define ASTRH 40      // A smem row stride in halves
#define BSTRH 40      // B smem row stride in halves

__global__ __launch_bounds__(256) void gemm_h(const __half* __restrict__ A,
                                              const __half* __restrict__ BT,
                                              __half* __restrict__ C16,
                                              int M, int N, int K, int reset_mx) {
    __shared__ __half As[2][TBM * ASTRH];
    __shared__ __half Bs[2][TBN * BSTRH];
    int tid = threadIdx.x;
    if (reset_mx && tid == 0 && blockIdx.x == 0 && blockIdx.y == 0) {
        g_mx[0] = 0u; g_mx[1] = 0u;
    }
    int lane = tid & 31, warp = tid >> 5;
    int wm = warp & 3, wn = warp >> 2;           // 4 (m) x 2 (n) warps
    int g = lane >> 2, t = lane & 3;
    int row0 = blockIdx.y * TBM, col0 = blockIdx.x * TBN;

    int ar = tid >> 2;          // 0..63
    int ac = (tid & 3) << 3;    // 0,8,16,24 halves
    unsigned as_base = (unsigned)__cvta_generic_to_shared(&As[0][0]);
    unsigned bs_base = (unsigned)__cvta_generic_to_shared(&Bs[0][0]);

    float c[2][4][4];
    #pragma unroll
    for (int i = 0; i < 2; i++)
        #pragma unroll
        for (int j = 0; j < 4; j++)
            #pragma unroll
            for (int k = 0; k < 4; k++) c[i][j][k] = 0.f;

    int nk = K / TBK;

    auto load_tile = [&](int buf, int k0) {
        #pragma unroll
        for (int i = 0; i < 2; i++) {
            int r = ar + i * 64;
            int gr = row0 + r;
            const __half* sp = (gr < M) ? (A + (size_t)gr * K + k0 + ac) : A;
            cp_async16(as_base + (buf * TBM * ASTRH + r * ASTRH + ac) * 2, sp);
        }
        {
            const __half* sp = BT + (size_t)(col0 + ar) * K + k0 + ac;
            cp_async16(bs_base + (buf * TBN * BSTRH + ar * BSTRH + ac) * 2, sp);
        }
    };

    load_tile(0, 0);
    cp_commit();

    for (int kt = 0; kt < nk; kt++) {
        int buf = kt & 1;
        if (kt + 1 < nk) { load_tile(buf ^ 1, (kt + 1) * TBK); cp_commit(); cp_wait1(); }
        else cp_wait0();
        __syncthreads();

        const __half* as = &As[buf][0];
        const __half* bs = &Bs[buf][0];
        #pragma unroll
        for (int ks = 0; ks < 2; ks++) {
            int kb = ks * 16;
            unsigned a[2][4], b[4][2];
            #pragma unroll
            for (int mt = 0; mt < 2; mt++) {
                int m0 = wm * 32 + mt * 16;
                a[mt][0] = *(const unsigned*)&as[(m0 + g)     * ASTRH + kb + 2 * t];
                a[mt][1] = *(const unsigned*)&as[(m0 + g + 8) * ASTRH + kb + 2 * t];
                a[mt][2] = *(const unsigned*)&as[(m0 + g)     * ASTRH + kb + 2 * t + 8];
                a[mt][3] = *(const unsigned*)&as[(m0 + g + 8) * ASTRH + kb + 2 * t + 8];
            }
            #pragma unroll
            for (int nt = 0; nt < 4; nt++) {
                int n0 = wn * 32 + nt * 8;
                b[nt][0] = *(const unsigned*)&bs[(n0 + g) * BSTRH + kb + 2 * t];
                b[nt][1] = *(const unsigned*)&bs[(n0 + g) * BSTRH + kb + 2 * t + 8];
            }
            #pragma unroll
            for (int mt = 0; mt < 2; mt++)
                #pragma unroll
                for (int nt = 0; nt < 4; nt++)
                    asm volatile(
                        "mma.sync.aligned.m16n8k16.row.col.f32.f16.f16.f32 "
                        "{%0,%1,%2,%3},{%4,%5,%6,%7},{%8,%9},{%0,%1,%2,%3};"
                        : "+f"(c[mt][nt][0]), "+f"(c[mt][nt][1]),
                          "+f"(c[mt][nt][2]), "+f"(c[mt][nt][3])
                        : "r"(a[mt][0]), "r"(a[mt][1]), "r"(a[mt][2]), "r"(a[mt][3]),
                          "r"(b[nt][0]), "r"(b[nt][1]));
        }
        __syncthreads();
    }

    #pragma unroll
    for (int mt = 0; mt < 2; mt++) {
        int rr = row0 + wm * 32 + mt * 16 + g;
        #pragma unroll
        for (int nt = 0; nt < 4; nt++) {
            int cc = col0 + wn * 32 + nt * 8 + 2 * t;
            if (rr < M && cc + 1 < N)
                *(__half2*)(C16 + (size_t)rr * N + cc) =
                    __floats2half2_rn(c[mt][nt][0], c[mt][nt][1]);
            if (rr + 8 < M && cc + 1 < N)
                *(__half2*)(C16 + (size_t)(rr + 8) * N + cc) =
                    __floats2half2_rn(c[mt][nt][2], c[mt][nt][3]);
        }
    }
}

// ---------------- el/er for 8-head layers (fp16 features): warp per node + global-max ----------------
__global__ void elr8_k(const __half* __restrict__ h16, const float* __restrict__ al,
                       const float* __restrict__ ar) {
    __shared__ float sm_el[8], sm_er[8];
    int warp = threadIdx.x >> 5;
    int w = blockIdx.x * 8 + warp;
    int lane = threadIdx.x & 31;
    uint4 hv = *(const uint4*)(h16 + (size_t)w * HF + lane * 8);
    float2 f0 = __half22float2(*(__half2*)&hv.x);
    float2 f1 = __half22float2(*(__half2*)&hv.y);
    float2 f2 = __half22float2(*(__half2*)&hv.z);
    float2 f3 = __half22float2(*(__half2*)&hv.w);
    const float4* alp = (const float4*)(al + lane * 8);
    const float4* arp = (const float4*)(ar + lane * 8);
    float4 l0 = alp[0], l1 = alp[1], r0 = arp[0], r1 = arp[1];
    float pel = f0.x*l0.x + f0.y*l0.y + f1.x*l0.z + f1.y*l0.w
              + f2.x*l1.x + f2.y*l1.y + f3.x*l1.z + f3.y*l1.w;
    float per = f0.x*r0.x + f0.y*r0.y + f1.x*r0.z + f1.y*r0.w
              + f2.x*r1.x + f2.y*r1.y + f3.x*r1.z + f3.y*r1.w;
    pel += __shfl_xor_sync(0xffffffffu, pel, 1);
    pel += __shfl_xor_sync(0xffffffffu, pel, 2);
    per += __shfl_xor_sync(0xffffffffu, per, 1);
    per += __shfl_xor_sync(0xffffffffu, per, 2);
    if ((lane & 3) == 0) {
        g_el[w * HEADS + (lane >> 2)] = pel;
        g_er[w * HEADS + (lane >> 2)] = per;
    }
    float mel = pel, mer = per;
    #pragma unroll
    for (int d = 4; d <= 16; d <<= 1) {
        mel = fmaxf(mel, __shfl_xor_sync(0xffffffffu, mel, d));
        mer = fmaxf(mer, __shfl_xor_sync(0xffffffffu, mer, d));
    }
    if (lane == 0) { sm_el[warp] = mel; sm_er[warp] = mer; }
    __syncthreads();
    if (warp == 0) {
        float vel = (lane < 8) ? sm_el[lane] : -INFINITY;
        float ver = (lane < 8) ? sm_er[lane] : -INFINITY;
        #pragma unroll
        for (int d = 1; d <= 4; d <<= 1) {
            vel = fmaxf(vel, __shfl_xor_sync(0xffffffffu, vel, d));
            ver = fmaxf(ver, __shfl_xor_sync(0xffffffffu, ver, d));
        }
        if (lane == 0) {
            atomicMax(&g_mx[0], fenc(vel));
            atomicMax(&g_mx[1], fenc(ver));
        }
    }
}

// ---------------- 8-head aggregation: warp per dst, single pass, uint4 fp16 gather ----------------
__global__ void agg8_k(const __half* __restrict__ h16, __half* __restrict__ out, int do_elu) {
    int w = (blockIdx.x * blockDim.x + threadIdx.x) >> 5;
    int lane = threadIdx.x & 31;
    if (w >= N_NODES) return;
    int head = lane >> 2;
    float M = lrelu(fdec(g_mx[0]) + fdec(g_mx[1]));   // global upper bound on all logits
    float erd = g_er[w * HEADS + head];
    int b = g_off[w], e = g_off[w + 1];
    float a0=0,a1=0,a2=0,a3=0,a4=0,a5=0,a6=0,a7=0, ss=0;
    for (int i = b; i < e; i++) {
        int s = g_ssrc[i];
        float ex = __expf(lrelu(g_el[s * HEADS + head] + erd) - M);
        ss += ex;
        uint4 hv = *(const uint4*)(h16 + (size_t)s * HF + lane * 8);
        float2 f0 = __half22float2(*(__half2*)&hv.x);
        float2 f1 = __half22float2(*(__half2*)&hv.y);
        float2 f2 = __half22float2(*(__half2*)&hv.z);
        float2 f3 = __half22float2(*(__half2*)&hv.w);
        a0 += ex*f0.x; a1 += ex*f0.y; a2 += ex*f1.x; a3 += ex*f1.y;
        a4 += ex*f2.x; a5 += ex*f2.y; a6 += ex*f3.x; a7 += ex*f3.y;
    }
    float inv = 1.f / (ss + 1e-16f);
    float r[8] = {a0*inv, a1*inv, a2*inv, a3*inv, a4*inv, a5*inv, a6*inv, a7*inv};
    if (do_elu) {
        #pragma unroll
        for (int k = 0; k < 8; k++) r[k] = r[k] > 0.f ? r[k] : expm1f(r[k]);
    }
    __half2 h01 = __floats2half2_rn(r[0], r[1]);
    __half2 h23 = __floats2half2_rn(r[2], r[3]);
    __half2 h45 = __floats2half2_rn(r[4], r[5]);
    __half2 h67 = __floats2half2_rn(r[6], r[7]);
    uint4 pk;
    pk.x = *(unsigned*)&h01; pk.y = *(unsigned*)&h23;
    pk.z = *(unsigned*)&h45; pk.w = *(unsigned*)&h67;
    *(uint4*)(out + (size_t)w * HF + lane * 8) = pk;
}

// ---------------- output layer el/er (H=1, F=40, fp16 feats): warp per node + global-max ----------------
__global__ void elro_k(const __half* __restrict__ h, const float* __restrict__ alo,
                       const float* __restrict__ aro) {
    __shared__ float sm_el[8], sm_er[8];
    int warp = threadIdx.x >> 5;
    int w = blockIdx.x * 8 + warp;
    int lane = threadIdx.x & 31;
    float v1 = __half2float(h[(size_t)w * N_CLASSES + lane]);
    float v2 = (lane < 8) ? __half2float(h[(size_t)w * N_CLASSES + 32 + lane]) : 0.f;
    float pel = v1 * alo[lane] + ((lane < 8) ? v2 * alo[32 + lane] : 0.f);
    float per = v1 * aro[lane] + ((lane < 8) ? v2 * aro[32 + lane] : 0.f);
    #pragma unroll
    for (int d = 16; d >= 1; d >>= 1) {
        pel += __shfl_xor_sync(0xffffffffu, pel, d);
        per += __shfl_xor_sync(0xffffffffu, per, d);
    }
    if (lane == 0) { g_el[w] = pel; g_er[w] = per; sm_el[warp] = pel; sm_er[warp] = per; }
    __syncthreads();
    if (warp == 0) {
        float vel = (lane < 8) ? sm_el[lane] : -INFINITY;
        float ver = (lane < 8) ? sm_er[lane] : -INFINITY;
        #pragma unroll
        for (int d = 1; d <= 4; d <<= 1) {
            vel = fmaxf(vel, __shfl_xor_sync(0xffffffffu, vel, d));
            ver = fmaxf(ver, __shfl_xor_sync(0xffffffffu, ver, d));
        }
        if (lane == 0) {
            atomicMax(&g_mx[0], fenc(vel));
            atomicMax(&g_mx[1], fenc(ver));
        }
    }
}

// ---------------- output aggregation + fused log_softmax (fp16 feats): warp per dst ----------------
__global__ void agg1ls_k(const __half* __restrict__ h, float* __restrict__ out) {
    int w = (blockIdx.x * blockDim.x + threadIdx.x) >> 5;
    int lane = threadIdx.x & 31;
    if (w >= N_NODES) return;
    float M = lrelu(fdec(g_mx[0]) + fdec(g_mx[1]));
    float erd = g_er[w];
    int b = g_off[w], e = g_off[w + 1];
    float a0 = 0, a1 = 0, ss = 0;
    for (int i = b; i < e; i++) {
        int s = g_ssrc[i];
        float ex = __expf(lrelu(g_el[s] + erd) - M);
        ss += ex;
        a0 += ex * __half2float(h[(size_t)s * N_CLASSES + lane]);
        if (lane < 8) a1 += ex * __half2float(h[(size_t)s * N_CLASSES + 32 + lane]);
    }
    float inv = 1.f / (ss + 1e-16f);
    float v1 = a0 * inv;
    float v2 = (lane < 8) ? a1 * inv : -INFINITY;
    float m = fmaxf(v1, v2);
    #pragma unroll
    for (int d = 16; d >= 1; d >>= 1) m = fmaxf(m, __shfl_xor_sync(0xffffffffu, m, d));
    float s = expf(v1 - m) + ((lane < 8) ? expf(v2 - m) : 0.f);
    #pragma unroll
    for (int d = 16; d >= 1; d >>= 1) s += __shfl_xor_sync(0xffffffffu, s, d);
    float ls = logf(s) + m;
    out[(size_t)w * N_CLASSES + lane] = v1 - ls;
    if (lane < 8) out[(size_t)w * N_CLASSES + 32 + lane] = v2 - ls;
}

// ---------------- host launcher ----------------
static inline int cdiv(int a, int b) { return (a + b - 1) / b; }

extern "C" void kernel_launch(void* const* d_in, const int* in_sizes, int n_in,
                              void* d_out, int out_size) {
    const float* x   = (const float*)d_in[0];
    const int*   src = (const int*)d_in[1];
    const int*   dst = (const int*)d_in[2];
    const float* W1  = (const float*)d_in[3];
    const float* al1 = (const float*)d_in[4];
    const float* ar1 = (const float*)d_in[5];
    const float* W2  = (const float*)d_in[6];
    const float* al2 = (const float*)d_in[7];
    const float* ar2 = (const float*)d_in[8];
    const float* Wo  = (const float*)d_in[9];
    const float* alo = (const float*)d_in[10];
    const float* aro = (const float*)d_in[11];
    float* out = (float*)d_out;

    void *pH16, *pQh, *pX16, *pW1T, *pW2T, *pWoT, *pO1h;
    cudaGetSymbolAddress(&pH16, g_h16);
    cudaGetSymbolAddress(&pQh, g_Qh);
    cudaGetSymbolAddress(&pX16, g_x16);
    cudaGetSymbolAddress(&pW1T, g_W1T);
    cudaGetSymbolAddress(&pW2T, g_W2T);
    cudaGetSymbolAddress(&pWoT, g_WoT);
    cudaGetSymbolAddress(&pO1h, g_o1h);

    // conversions (cvtA also zeroes g_cnt/g_cur; cvtW fuses all 3 weight transposes)
    cvtA_k<<<cdiv(N_NODES * IN_F, 256), 256>>>(x, (__half*)pX16, N_NODES * IN_F);
    cvtW_k<<<cdiv(WALL_ELEMS, 256), 256>>>(W1, W2, Wo);

    // CSR build (by dst) with multi-block scan
    int eb = cdiv(N_EDGES, 256);
    hist_k<<<eb, 256>>>(dst);
    scan1_k<<<NBLK, SCAN_B>>>();
    scan2_k<<<1, 64>>>();
    scan3_k<<<NBLK, SCAN_B>>>();
    scatter_k<<<eb, 256>>>(src, dst);

    int nwb = N_NODES * 32 / 256;            // 6250 blocks, 8 warps each
    dim3 g1(cdiv(HF, TBN), cdiv(N_NODES, TBM));      // 4 x 391
    dim3 g3(1, cdiv(N_NODES, TBM));                   // N=40 -> 1 col tile

    // layer 1: fp16 GEMM -> fp16 features (also resets g_mx)
    gemm_h<<<g1, 256>>>((const __half*)pX16, (const __half*)pW1T, (__half*)pH16,
                        N_NODES, HF, IN_F, 1);
    elr8_k<<<nwb, 256>>>((const __half*)pH16, al1, ar1);
    agg8_k<<<nwb, 256>>>((const __half*)pH16, (__half*)pQh, 1);

    // layer 2
    gemm_h<<<g1, 256>>>((const __half*)pQh, (const __half*)pW2T, (__half*)pH16,
                        N_NODES, HF, HF, 1);
    elr8_k<<<nwb, 256>>>((const __half*)pH16, al2, ar2);
    agg8_k<<<nwb, 256>>>((const __half*)pH16, (__half*)pQh, 1);

    // output layer: fp16 GEMM -> fp16 logits; fp32 math downstream (GEMM resets g_mx)
    gemm_h<<<g3, 256>>>((const __half*)pQh, (const __half*)pWoT, (__half*)pO1h,
                        N_NODES, N_CLASSES, HF, 1);
    elro_k<<<nwb, 256>>>((const __half*)pO1h, alo, aro);
    agg1ls_k<<<nwb, 256>>>((const __half*)pO1h, out);
}